// round 1
// baseline (speedup 1.0000x reference)
#include <cuda_runtime.h>
#include <cuda_bf16.h>
#include <mma.h>
#include <math.h>

using namespace nvcuda;

// ---------------- problem constants ----------------
#define BATCH   2
#define TSEQ    2048
#define R_TOT   4096          // BATCH*TSEQ
#define E       2048          // n_embd
#define DI      4096          // d_inner
#define HH      32            // n_heads
#define PP      128           // head_dim
#define NS      128           // d_state
#define QQ      64            // chunk
#define NC      32            // chunks per batch (TSEQ/QQ)
#define PROJW   8480          // 2*DI + HH + 2*NS
#define WPAD    8576          // PROJW padded to multiple of 128
#define DCONV   4

// ---------------- scratch (device globals; no allocation allowed) ----------------
__device__ __nv_bfloat16 g_h[(size_t)R_TOT * E];          // normalized input, bf16
__device__ __nv_bfloat16 g_w1[(size_t)E * WPAD];          // in_proj_w bf16, padded
__device__ __nv_bfloat16 g_w2[(size_t)DI * E];            // out_proj_w bf16
__device__ float         g_proj[(size_t)R_TOT * WPAD];    // projection output
__device__ float         g_act[(size_t)R_TOT * DI];       // conv+silu output (x for SSD)
__device__ float         g_y[(size_t)R_TOT * DI];         // y_intra accumulator
__device__ __nv_bfloat16 g_yb[(size_t)R_TOT * DI];        // gated y, bf16 for GEMM2
__device__ float         g_state[(size_t)BATCH * NC * HH * NS * PP]; // chunk states
__device__ float         g_cdecay[BATCH * NC * HH];
__device__ float         g_cum[(size_t)R_TOT * HH];       // cumulative log decay

// ---------------- weight conversion ----------------
__global__ void conv_w1_k(const float* __restrict__ w) {
    size_t idx = (size_t)blockIdx.x * 256 + threadIdx.x;
    if (idx >= (size_t)E * WPAD) return;
    int row = (int)(idx / WPAD);
    int col = (int)(idx % WPAD);
    float v = (col < PROJW) ? w[(size_t)row * PROJW + col] : 0.f;
    g_w1[idx] = __float2bfloat16(v);
}

__global__ void conv_w2_k(const float* __restrict__ w) {
    size_t idx = (size_t)blockIdx.x * 256 + threadIdx.x;
    if (idx >= (size_t)DI * E) return;
    g_w2[idx] = __float2bfloat16(w[idx]);
}

// ---------------- rmsnorm (block per row) ----------------
__global__ void rmsnorm_k(const float* __restrict__ x, const float* __restrict__ scale) {
    int r = blockIdx.x;
    int tid = threadIdx.x;
    const float* xr = x + (size_t)r * E;
    __shared__ float red[256];
    float ss = 0.f;
    for (int i = tid; i < E; i += 256) { float v = xr[i]; ss += v * v; }
    red[tid] = ss; __syncthreads();
    for (int s = 128; s > 0; s >>= 1) {
        if (tid < s) red[tid] += red[tid + s];
        __syncthreads();
    }
    float rstd = rsqrtf(red[0] / (float)E + 1e-6f);
    for (int i = tid; i < E; i += 256)
        g_h[(size_t)r * E + i] = __float2bfloat16(xr[i] * rstd * scale[i]);
}

// ---------------- bf16 WMMA GEMM: C = A @ B (+ residual) ----------------
// A: MxK row-major bf16 (lda), B: KxN row-major bf16 (ldb), C: MxN fp32 (ldc).
// 128x128 block tile, BK=32, 8 warps in 2x4, each warp 64x32 (4x2 frags).
__global__ __launch_bounds__(256) void gemm_bf16(
    const __nv_bfloat16* __restrict__ A, const __nv_bfloat16* __restrict__ Bw,
    float* __restrict__ C, const float* __restrict__ res,
    int M, int N, int K, int lda, int ldb, int ldc, int add_res)
{
    __shared__ __nv_bfloat16 sA[128 * 40];
    __shared__ __nv_bfloat16 sB[32 * 136];

    int tid = threadIdx.x;
    int wid = tid >> 5;
    int warp_m = wid >> 2;   // 0..1
    int warp_n = wid & 3;    // 0..3
    int row0 = blockIdx.y * 128;
    int col0 = blockIdx.x * 128;

    wmma::fragment<wmma::accumulator, 16, 16, 16, float> acc[4][2];
    if (add_res) {
        #pragma unroll
        for (int i = 0; i < 4; i++)
            #pragma unroll
            for (int j = 0; j < 2; j++) {
                const float* p = res + (size_t)(row0 + warp_m * 64 + i * 16) * ldc
                                     + col0 + warp_n * 32 + j * 16;
                wmma::load_matrix_sync(acc[i][j], p, ldc, wmma::mem_row_major);
            }
    } else {
        #pragma unroll
        for (int i = 0; i < 4; i++)
            #pragma unroll
            for (int j = 0; j < 2; j++)
                wmma::fill_fragment(acc[i][j], 0.f);
    }

    for (int k0 = 0; k0 < K; k0 += 32) {
        // load A tile 128x32 (16B vectors)
        #pragma unroll
        for (int it = 0; it < 2; it++) {
            int e = (tid + it * 256) * 8;
            int r = e >> 5, c = e & 31;
            uint4 v = *(const uint4*)(A + (size_t)(row0 + r) * lda + k0 + c);
            *(uint4*)(sA + r * 40 + c) = v;
        }
        // load B tile 32x128
        #pragma unroll
        for (int it = 0; it < 2; it++) {
            int e = (tid + it * 256) * 8;
            int r = e >> 7, c = e & 127;
            uint4 v = *(const uint4*)(Bw + (size_t)(k0 + r) * ldb + col0 + c);
            *(uint4*)(sB + r * 136 + c) = v;
        }
        __syncthreads();

        #pragma unroll
        for (int kk = 0; kk < 32; kk += 16) {
            wmma::fragment<wmma::matrix_a, 16, 16, 16, __nv_bfloat16, wmma::row_major> af[4];
            wmma::fragment<wmma::matrix_b, 16, 16, 16, __nv_bfloat16, wmma::row_major> bf[2];
            #pragma unroll
            for (int i = 0; i < 4; i++)
                wmma::load_matrix_sync(af[i], sA + (warp_m * 64 + i * 16) * 40 + kk, 40);
            #pragma unroll
            for (int j = 0; j < 2; j++)
                wmma::load_matrix_sync(bf[j], sB + kk * 136 + warp_n * 32 + j * 16, 136);
            #pragma unroll
            for (int i = 0; i < 4; i++)
                #pragma unroll
                for (int j = 0; j < 2; j++)
                    wmma::mma_sync(acc[i][j], af[i], bf[j], acc[i][j]);
        }
        __syncthreads();
    }

    #pragma unroll
    for (int i = 0; i < 4; i++)
        #pragma unroll
        for (int j = 0; j < 2; j++) {
            float* p = C + (size_t)(row0 + warp_m * 64 + i * 16) * ldc
                         + col0 + warp_n * 32 + j * 16;
            wmma::store_matrix_sync(p, acc[i][j], ldc, wmma::mem_row_major);
        }
}

// ---------------- causal depthwise conv (width 4) + bias + silu ----------------
__global__ void conv_silu_k(const float* __restrict__ cw, const float* __restrict__ cb) {
    size_t idx = (size_t)blockIdx.x * 256 + threadIdx.x;
    if (idx >= (size_t)R_TOT * DI) return;
    int d = (int)(idx & (DI - 1));
    int r = (int)(idx >> 12);
    int t = r & (TSEQ - 1);
    float acc = cb[d];
    #pragma unroll
    for (int k = 0; k < DCONV; k++) {
        int tt = t - 3 + k;
        if (tt >= 0)
            acc += g_proj[(size_t)(r - 3 + k) * WPAD + DI + d] * cw[k * DI + d];
    }
    g_act[idx] = acc / (1.f + expf(-acc)); // silu
}

// ---------------- SSD pass1: per (b,chunk,head) intra-chunk work ----------------
// dyn smem: sB[64*129] sC[64*129] sX[64*129] sM[64*64] sdt[64] scum[64] sw[64]
__global__ __launch_bounds__(256) void ssd_pass1_k(
    const float* __restrict__ A_log, const float* __restrict__ dt_bias)
{
    extern __shared__ float sm[];
    float* sB  = sm;
    float* sC  = sB + 64 * 129;
    float* sX  = sC + 64 * 129;
    float* sM  = sX + 64 * 129;       // 64*64, holds M[i][j]
    float* sdt = sM + 4096;
    float* scum = sdt + 64;
    float* sw  = scum + 64;

    int h = blockIdx.x, c = blockIdx.y, b = blockIdx.z;
    int tid = threadIdx.x;
    int r0 = b * TSEQ + c * QQ;

    // ---- dt + cumulative log-decay ----
    if (tid < QQ) {
        float d = g_proj[(size_t)(r0 + tid) * WPAD + 2 * DI + h] + dt_bias[h];
        float dt = (d > 20.f) ? d : log1pf(expf(d));
        sdt[tid] = dt;
        float Ah = -expf(A_log[h]);
        scum[tid] = Ah * dt;
    }
    __syncthreads();
    for (int off = 1; off < QQ; off <<= 1) {
        float add = 0.f;
        if (tid < QQ && tid >= off) add = scum[tid - off];
        __syncthreads();
        if (tid < QQ) scum[tid] += add;
        __syncthreads();
    }
    if (tid < QQ) g_cum[(size_t)(r0 + tid) * HH + h] = scum[tid];

    // ---- load B, C, X tiles ----
    for (int idx = tid; idx < QQ * NS; idx += 256) {
        int row = idx >> 7, col = idx & 127;
        size_t pb = (size_t)(r0 + row) * WPAD;
        sB[row * 129 + col] = g_proj[pb + 2 * DI + HH + col];
        sC[row * 129 + col] = g_proj[pb + 2 * DI + HH + NS + col];
        sX[row * 129 + col] = g_act[(size_t)(r0 + row) * DI + h * PP + col];
    }
    __syncthreads();

    // ---- M[i][j] = exp(cum_i - cum_j) * (C_i . B_j) * dt_j  (lower tri) ----
    for (int e = tid; e < QQ * QQ; e += 256) {
        int i = e >> 6, j = e & 63;
        float m = 0.f;
        if (j <= i) {
            float s = 0.f;
            #pragma unroll 8
            for (int n = 0; n < NS; n++) s += sC[i * 129 + n] * sB[j * 129 + n];
            m = s * expf(scum[i] - scum[j]) * sdt[j];
        }
        sM[e] = m;
    }
    __syncthreads();

    float clast = scum[QQ - 1];
    // weights for state_local (compute while y_intra runs; no B reads before next sync)
    if (tid < QQ) sw[tid] = expf(clast - scum[tid]) * sdt[tid];
    if (tid == 0) g_cdecay[(b * NC + c) * HH + h] = expf(clast);

    // ---- y_intra = M @ X ----
    for (int o = tid; o < QQ * PP; o += 256) {
        int i = o >> 7, p = o & 127;
        float s = 0.f;
        #pragma unroll 8
        for (int j = 0; j < QQ; j++) s += sM[i * 64 + j] * sX[j * 129 + p];
        g_y[(size_t)(r0 + i) * DI + h * PP + p] = s;
    }
    __syncthreads();

    // ---- scale B rows by w[j] ----
    for (int idx = tid; idx < QQ * NS; idx += 256) {
        int row = idx >> 7, col = idx & 127;
        sB[row * 129 + col] *= sw[row];
    }
    __syncthreads();

    // ---- state_local[n][p] = sum_j wB[j][n] * X[j][p] ----
    size_t sbase = (size_t)((b * NC + c) * HH + h) * (NS * PP);
    for (int o = tid; o < NS * PP; o += 256) {
        int n = o >> 7, p = o & 127;
        float s = 0.f;
        #pragma unroll 8
        for (int j = 0; j < QQ; j++) s += sB[j * 129 + n] * sX[j * 129 + p];
        g_state[sbase + o] = s;
    }
}

// ---------------- SSD pass2: sequential inter-chunk scan ----------------
// block per (b,h); overwrites g_state[c] with the state at chunk START.
__global__ __launch_bounds__(512) void ssd_scan_k() {
    int h = blockIdx.x, b = blockIdx.y;
    int tid = threadIdx.x;
    float st[32];
    #pragma unroll
    for (int k = 0; k < 32; k++) st[k] = 0.f;
    for (int c = 0; c < NC; c++) {
        size_t base = (size_t)((b * NC + c) * HH + h) * (NS * PP);
        float dcy = g_cdecay[(b * NC + c) * HH + h];
        #pragma unroll
        for (int k = 0; k < 32; k++) {
            size_t idx = base + tid + k * 512;
            float loc = g_state[idx];
            g_state[idx] = st[k];                 // state at chunk start
            st[k] = fmaf(dcy, st[k], loc);
        }
    }
}

// ---------------- SSD pass3: y_inter + D*x + gate, write bf16 ----------------
// dyn smem: sS[128*129] sC[64*129] scum[64]
__global__ __launch_bounds__(256) void ssd_pass3_k(const float* __restrict__ Dv) {
    extern __shared__ float sm[];
    float* sS = sm;                    // 128*129
    float* sC = sS + NS * 129;         // 64*129
    float* scum = sC + QQ * 129;       // 64

    int h = blockIdx.x, c = blockIdx.y, b = blockIdx.z;
    int tid = threadIdx.x;
    int r0 = b * TSEQ + c * QQ;
    size_t sbase = (size_t)((b * NC + c) * HH + h) * (NS * PP);

    for (int idx = tid; idx < NS * PP; idx += 256) {
        int row = idx >> 7, col = idx & 127;
        sS[row * 129 + col] = g_state[sbase + idx];
    }
    for (int idx = tid; idx < QQ * NS; idx += 256) {
        int row = idx >> 7, col = idx & 127;
        sC[row * 129 + col] = g_proj[(size_t)(r0 + row) * WPAD + 2 * DI + HH + NS + col];
    }
    if (tid < QQ) scum[tid] = g_cum[(size_t)(r0 + tid) * HH + h];
    __syncthreads();

    for (int o = tid; o < QQ * PP; o += 256) {
        int i = o >> 7, p = o & 127;
        float s = 0.f;
        #pragma unroll 8
        for (int n = 0; n < NS; n++) s += sC[i * 129 + n] * sS[n * 129 + p];
        float yi = expf(scum[i]) * s;
        int d = h * PP + p;
        size_t r = (size_t)(r0 + i);
        float act = g_act[r * DI + d];
        float val = g_y[r * DI + d] + yi + Dv[d] * act;
        float gate = g_proj[r * WPAD + d];
        float sg = gate / (1.f + expf(-gate));
        g_yb[r * DI + d] = __float2bfloat16(val * sg);
    }
}

// ---------------- launch ----------------
extern "C" void kernel_launch(void* const* d_in, const int* in_sizes, int n_in,
                              void* d_out, int out_size) {
    const float* x         = (const float*)d_in[0];
    const float* normscale = (const float*)d_in[1];
    const float* w1        = (const float*)d_in[2];
    const float* convw     = (const float*)d_in[3];
    const float* convb     = (const float*)d_in[4];
    const float* A_log     = (const float*)d_in[5];
    const float* dt_bias   = (const float*)d_in[6];
    const float* Dv        = (const float*)d_in[7];
    const float* w2        = (const float*)d_in[8];
    float* out             = (float*)d_out;

    void *p_h, *p_w1, *p_w2, *p_proj, *p_yb;
    cudaGetSymbolAddress(&p_h, g_h);
    cudaGetSymbolAddress(&p_w1, g_w1);
    cudaGetSymbolAddress(&p_w2, g_w2);
    cudaGetSymbolAddress(&p_proj, g_proj);
    cudaGetSymbolAddress(&p_yb, g_yb);

    const int smem1 = (3 * 64 * 129 + 4096 + 3 * 64) * 4;           // pass1
    const int smem3 = (128 * 129 + 64 * 129 + 64) * 4;              // pass3
    cudaFuncSetAttribute(ssd_pass1_k, cudaFuncAttributeMaxDynamicSharedMemorySize, smem1);
    cudaFuncSetAttribute(ssd_pass3_k, cudaFuncAttributeMaxDynamicSharedMemorySize, smem3);

    // 1. weight conversion
    {
        size_t n1 = (size_t)E * WPAD;
        conv_w1_k<<<(unsigned)((n1 + 255) / 256), 256>>>(w1);
        size_t n2 = (size_t)DI * E;
        conv_w2_k<<<(unsigned)((n2 + 255) / 256), 256>>>(w2);
    }
    // 2. rmsnorm -> g_h (bf16)
    rmsnorm_k<<<R_TOT, 256>>>(x, normscale);
    // 3. in_proj GEMM -> g_proj
    {
        dim3 grid(WPAD / 128, R_TOT / 128);
        gemm_bf16<<<grid, 256>>>((const __nv_bfloat16*)p_h, (const __nv_bfloat16*)p_w1,
                                 (float*)p_proj, nullptr,
                                 R_TOT, WPAD, E, E, WPAD, WPAD, 0);
    }
    // 4. conv + silu -> g_act
    {
        size_t n = (size_t)R_TOT * DI;
        conv_silu_k<<<(unsigned)((n + 255) / 256), 256>>>(convw, convb);
    }
    // 5. SSD intra-chunk
    {
        dim3 grid(HH, NC, BATCH);
        ssd_pass1_k<<<grid, 256, smem1>>>(A_log, dt_bias);
    }
    // 6. inter-chunk scan
    {
        dim3 grid(HH, BATCH);
        ssd_scan_k<<<grid, 512>>>();
    }
    // 7. y_inter + epilogue -> g_yb (bf16)
    {
        dim3 grid(HH, NC, BATCH);
        ssd_pass3_k<<<grid, 256, smem3>>>(Dv);
    }
    // 8. out_proj GEMM + residual -> d_out
    {
        dim3 grid(E / 128, R_TOT / 128);
        gemm_bf16<<<grid, 256>>>((const __nv_bfloat16*)p_yb, (const __nv_bfloat16*)p_w2,
                                 out, x,
                                 R_TOT, E, DI, DI, E, E, 1);
    }
}

// round 6
// speedup vs baseline: 1.7650x; 1.7650x over previous
#include <cstdint>
#include <cuda_runtime.h>
#include <cuda_bf16.h>
#include <mma.h>
#include <math.h>

using namespace nvcuda;

// ---------------- problem constants ----------------
#define BATCH   2
#define TSEQ    2048
#define R_TOT   4096
#define E       2048
#define DI      4096
#define HH      32
#define PP      128
#define NS      128
#define QQ      64
#define NC      32
#define PROJW   8480
#define WPAD    8576
#define DCONV   4

#define TS      136      // bf16 tile stride (mult of 8 for WMMA)
#define MS      72       // M tile stride
#define YS      132      // fp32 y tile stride (mult of 4)

// ---------------- scratch ----------------
__device__ __nv_bfloat16 g_h[(size_t)R_TOT * E];
__device__ __nv_bfloat16 g_w1[(size_t)E * WPAD];
__device__ __nv_bfloat16 g_w2[(size_t)DI * E];
__device__ float         g_proj[(size_t)R_TOT * WPAD];
__device__ float         g_act[(size_t)R_TOT * DI];
__device__ float         g_y[(size_t)R_TOT * DI];
__device__ __nv_bfloat16 g_yb[(size_t)R_TOT * DI];
__device__ float         g_state[(size_t)BATCH * NC * HH * NS * PP];
__device__ float         g_cdecay[BATCH * NC * HH];
__device__ float         g_cum[(size_t)R_TOT * HH];

// ---------------- cp.async helpers ----------------
__device__ __forceinline__ void cpa16(void* dst, const void* src) {
    unsigned int d = (unsigned int)__cvta_generic_to_shared(dst);
    asm volatile("cp.async.cg.shared.global [%0], [%1], 16;\n" :: "r"(d), "l"(src));
}
#define CP_COMMIT() asm volatile("cp.async.commit_group;\n" ::: "memory")
#define CP_WAIT0()  asm volatile("cp.async.wait_group 0;\n" ::: "memory")

// ---------------- weight conversion ----------------
__global__ void conv_w1_k(const float* __restrict__ w) {
    size_t idx = (size_t)blockIdx.x * 256 + threadIdx.x;
    if (idx >= (size_t)E * WPAD) return;
    int row = (int)(idx / WPAD);
    int col = (int)(idx % WPAD);
    float v = (col < PROJW) ? w[(size_t)row * PROJW + col] : 0.f;
    g_w1[idx] = __float2bfloat16(v);
}
__global__ void conv_w2_k(const float* __restrict__ w) {
    size_t idx = (size_t)blockIdx.x * 256 + threadIdx.x;
    if (idx >= (size_t)DI * E) return;
    g_w2[idx] = __float2bfloat16(w[idx]);
}

// ---------------- rmsnorm ----------------
__global__ void rmsnorm_k(const float* __restrict__ x, const float* __restrict__ scale) {
    int r = blockIdx.x;
    int tid = threadIdx.x;
    const float* xr = x + (size_t)r * E;
    __shared__ float red[256];
    float ss = 0.f;
    for (int i = tid; i < E; i += 256) { float v = xr[i]; ss += v * v; }
    red[tid] = ss; __syncthreads();
    for (int s = 128; s > 0; s >>= 1) {
        if (tid < s) red[tid] += red[tid + s];
        __syncthreads();
    }
    float rstd = rsqrtf(red[0] / (float)E + 1e-6f);
    for (int i = tid; i < E; i += 256)
        g_h[(size_t)r * E + i] = __float2bfloat16(xr[i] * rstd * scale[i]);
}

// ---------------- double-buffered bf16 WMMA GEMM ----------------
__global__ __launch_bounds__(256) void gemm_bf16(
    const __nv_bfloat16* __restrict__ A, const __nv_bfloat16* __restrict__ Bw,
    float* __restrict__ C, const float* __restrict__ res,
    int M, int N, int K, int lda, int ldb, int ldc, int add_res)
{
    __shared__ __nv_bfloat16 sA[2][128 * 40];
    __shared__ __nv_bfloat16 sB[2][32 * 136];

    int tid = threadIdx.x;
    int wid = tid >> 5;
    int warp_m = wid >> 2;
    int warp_n = wid & 3;
    int row0 = blockIdx.y * 128;
    int col0 = blockIdx.x * 128;

    wmma::fragment<wmma::accumulator, 16, 16, 16, float> acc[4][2];
    if (add_res) {
        #pragma unroll
        for (int i = 0; i < 4; i++)
            #pragma unroll
            for (int j = 0; j < 2; j++) {
                const float* p = res + (size_t)(row0 + warp_m * 64 + i * 16) * ldc
                                     + col0 + warp_n * 32 + j * 16;
                wmma::load_matrix_sync(acc[i][j], p, ldc, wmma::mem_row_major);
            }
    } else {
        #pragma unroll
        for (int i = 0; i < 4; i++)
            #pragma unroll
            for (int j = 0; j < 2; j++)
                wmma::fill_fragment(acc[i][j], 0.f);
    }

    // prologue: load stage 0
    {
        #pragma unroll
        for (int it = 0; it < 2; it++) {
            int e = (tid + it * 256) * 8;
            int r = e >> 5, c = e & 31;
            cpa16(&sA[0][r * 40 + c], A + (size_t)(row0 + r) * lda + c);
        }
        #pragma unroll
        for (int it = 0; it < 2; it++) {
            int e = (tid + it * 256) * 8;
            int r = e >> 7, c = e & 127;
            cpa16(&sB[0][r * 136 + c], Bw + (size_t)r * ldb + col0 + c);
        }
        CP_COMMIT();
    }

    int buf = 0;
    for (int k0 = 0; k0 < K; k0 += 32) {
        CP_WAIT0();
        __syncthreads();
        if (k0 + 32 < K) {
            int kn = k0 + 32;
            #pragma unroll
            for (int it = 0; it < 2; it++) {
                int e = (tid + it * 256) * 8;
                int r = e >> 5, c = e & 31;
                cpa16(&sA[buf ^ 1][r * 40 + c], A + (size_t)(row0 + r) * lda + kn + c);
            }
            #pragma unroll
            for (int it = 0; it < 2; it++) {
                int e = (tid + it * 256) * 8;
                int r = e >> 7, c = e & 127;
                cpa16(&sB[buf ^ 1][r * 136 + c], Bw + (size_t)(kn + r) * ldb + col0 + c);
            }
            CP_COMMIT();
        }
        #pragma unroll
        for (int kk = 0; kk < 32; kk += 16) {
            wmma::fragment<wmma::matrix_a, 16, 16, 16, __nv_bfloat16, wmma::row_major> af[4];
            wmma::fragment<wmma::matrix_b, 16, 16, 16, __nv_bfloat16, wmma::row_major> bf[2];
            #pragma unroll
            for (int i = 0; i < 4; i++)
                wmma::load_matrix_sync(af[i], &sA[buf][(warp_m * 64 + i * 16) * 40 + kk], 40);
            #pragma unroll
            for (int j = 0; j < 2; j++)
                wmma::load_matrix_sync(bf[j], &sB[buf][kk * 136 + warp_n * 32 + j * 16], 136);
            #pragma unroll
            for (int i = 0; i < 4; i++)
                #pragma unroll
                for (int j = 0; j < 2; j++)
                    wmma::mma_sync(acc[i][j], af[i], bf[j], acc[i][j]);
        }
        buf ^= 1;
    }

    #pragma unroll
    for (int i = 0; i < 4; i++)
        #pragma unroll
        for (int j = 0; j < 2; j++) {
            float* p = C + (size_t)(row0 + warp_m * 64 + i * 16) * ldc
                         + col0 + warp_n * 32 + j * 16;
            wmma::store_matrix_sync(p, acc[i][j], ldc, wmma::mem_row_major);
        }
}

// ---------------- conv + silu ----------------
__global__ void conv_silu_k(const float* __restrict__ cw, const float* __restrict__ cb) {
    size_t idx = (size_t)blockIdx.x * 256 + threadIdx.x;
    if (idx >= (size_t)R_TOT * DI) return;
    int d = (int)(idx & (DI - 1));
    int r = (int)(idx >> 12);
    int t = r & (TSEQ - 1);
    float acc = cb[d];
    #pragma unroll
    for (int k = 0; k < DCONV; k++) {
        int tt = t - 3 + k;
        if (tt >= 0)
            acc += g_proj[(size_t)(r - 3 + k) * WPAD + DI + d] * cw[k * DI + d];
    }
    g_act[idx] = acc / (1.f + expf(-acc));
}

// ---------------- SSD pass1 (WMMA): per (b,chunk,head) ----------------
__global__ __launch_bounds__(256) void ssd_pass1_k(
    const float* __restrict__ A_log, const float* __restrict__ dt_bias)
{
    extern __shared__ char smraw[];
    __nv_bfloat16* sB  = (__nv_bfloat16*)smraw;           // 64*TS
    __nv_bfloat16* sC  = sB + QQ * TS;
    __nv_bfloat16* sX  = sC + QQ * TS;
    __nv_bfloat16* sWB = sX + QQ * TS;
    __nv_bfloat16* sMb = sWB + QQ * TS;                   // 64*MS
    float* sMf  = (float*)(sMb + QQ * MS);                // 64*MS fp32
    float* sdt  = sMf + QQ * MS;
    float* scum = sdt + QQ;
    float* sw   = scum + QQ;

    int h = blockIdx.x, c = blockIdx.y, b = blockIdx.z;
    int tid = threadIdx.x;
    int wid = tid >> 5;
    int r0 = b * TSEQ + c * QQ;

    // ---- phase A: dt + cumulative log decay ----
    if (tid < QQ) {
        float d = g_proj[(size_t)(r0 + tid) * WPAD + 2 * DI + h] + dt_bias[h];
        float dt = (d > 20.f) ? d : log1pf(expf(d));
        sdt[tid] = dt;
        scum[tid] = -expf(A_log[h]) * dt;
    }
    __syncthreads();
    for (int off = 1; off < QQ; off <<= 1) {
        float add = 0.f;
        if (tid < QQ && tid >= off) add = scum[tid - off];
        __syncthreads();
        if (tid < QQ) scum[tid] += add;
        __syncthreads();
    }
    if (tid < QQ) {
        g_cum[(size_t)(r0 + tid) * HH + h] = scum[tid];
        float clast = scum[QQ - 1];
        sw[tid] = expf(clast - scum[tid]) * sdt[tid];
        if (tid == 0) g_cdecay[(b * NC + c) * HH + h] = expf(clast);
    }
    __syncthreads();

    // ---- load tiles (fp32 -> bf16), WB = B * w[row] ----
    for (int idx = tid; idx < QQ * NS; idx += 256) {
        int row = idx >> 7, col = idx & 127;
        size_t pb = (size_t)(r0 + row) * WPAD;
        float bv = g_proj[pb + 2 * DI + HH + col];
        float cv = g_proj[pb + 2 * DI + HH + NS + col];
        float xv = g_act[(size_t)(r0 + row) * DI + h * PP + col];
        sB[row * TS + col]  = __float2bfloat16(bv);
        sC[row * TS + col]  = __float2bfloat16(cv);
        sX[row * TS + col]  = __float2bfloat16(xv);
        sWB[row * TS + col] = __float2bfloat16(bv * sw[row]);
    }
    __syncthreads();

    // ---- phase C: CB = C @ B^T  (64x64, k=128), WMMA ----
    {
        int wm = wid >> 1;  // 0..3 -> rows wm*16
        int wn = wid & 1;   // 0..1 -> cols wn*32
        wmma::fragment<wmma::accumulator, 16, 16, 16, float> acc2[2];
        wmma::fill_fragment(acc2[0], 0.f);
        wmma::fill_fragment(acc2[1], 0.f);
        #pragma unroll
        for (int k = 0; k < 8; k++) {
            wmma::fragment<wmma::matrix_a, 16, 16, 16, __nv_bfloat16, wmma::row_major> a;
            wmma::load_matrix_sync(a, sC + (wm * 16) * TS + k * 16, TS);
            #pragma unroll
            for (int j2 = 0; j2 < 2; j2++) {
                wmma::fragment<wmma::matrix_b, 16, 16, 16, __nv_bfloat16, wmma::col_major> bfr;
                wmma::load_matrix_sync(bfr, sB + (wn * 32 + j2 * 16) * TS + k * 16, TS);
                wmma::mma_sync(acc2[j2], a, bfr, acc2[j2]);
            }
        }
        #pragma unroll
        for (int j2 = 0; j2 < 2; j2++)
            wmma::store_matrix_sync(sMf + (wm * 16) * MS + wn * 32 + j2 * 16, acc2[j2],
                                    MS, wmma::mem_row_major);
    }
    __syncthreads();

    // ---- elementwise: M = mask * exp(cum_i - cum_j) * CB * dt_j -> bf16 ----
    for (int e = tid; e < QQ * QQ; e += 256) {
        int i = e >> 6, j = e & 63;
        float m = 0.f;
        if (j <= i)
            m = sMf[i * MS + j] * expf(scum[i] - scum[j]) * sdt[j];
        sMb[i * MS + j] = __float2bfloat16(m);
    }
    __syncthreads();

    // ---- phase D: y_intra = M @ X (64x128, k=64) -> g_y ----
    {
        int wm = wid >> 1;  // rows wm*16
        int wn = wid & 1;   // cols wn*64
        wmma::fragment<wmma::accumulator, 16, 16, 16, float> acc4[4];
        #pragma unroll
        for (int j = 0; j < 4; j++) wmma::fill_fragment(acc4[j], 0.f);
        #pragma unroll
        for (int k = 0; k < 4; k++) {
            wmma::fragment<wmma::matrix_a, 16, 16, 16, __nv_bfloat16, wmma::row_major> a;
            wmma::load_matrix_sync(a, sMb + (wm * 16) * MS + k * 16, MS);
            #pragma unroll
            for (int jj = 0; jj < 4; jj++) {
                wmma::fragment<wmma::matrix_b, 16, 16, 16, __nv_bfloat16, wmma::row_major> bfr;
                wmma::load_matrix_sync(bfr, sX + (k * 16) * TS + wn * 64 + jj * 16, TS);
                wmma::mma_sync(acc4[jj], a, bfr, acc4[jj]);
            }
        }
        #pragma unroll
        for (int jj = 0; jj < 4; jj++) {
            float* p = g_y + (size_t)(r0 + wm * 16) * DI + h * PP + wn * 64 + jj * 16;
            wmma::store_matrix_sync(p, acc4[jj], DI, wmma::mem_row_major);
        }
    }

    // ---- phase F: state = WB^T @ X (128x128, k=64) -> g_state ----
    {
        int wm = wid >> 1;  // n rows wm*32 (2 tiles)
        int wn = wid & 1;   // p cols wn*64 (4 tiles)
        size_t sbase = (size_t)((b * NC + c) * HH + h) * (NS * PP);
        wmma::fragment<wmma::accumulator, 16, 16, 16, float> accs[2][4];
        #pragma unroll
        for (int i2 = 0; i2 < 2; i2++)
            #pragma unroll
            for (int jj = 0; jj < 4; jj++) wmma::fill_fragment(accs[i2][jj], 0.f);
        #pragma unroll
        for (int k = 0; k < 4; k++) {
            wmma::fragment<wmma::matrix_a, 16, 16, 16, __nv_bfloat16, wmma::col_major> a[2];
            #pragma unroll
            for (int i2 = 0; i2 < 2; i2++)
                wmma::load_matrix_sync(a[i2], sWB + (k * 16) * TS + wm * 32 + i2 * 16, TS);
            #pragma unroll
            for (int jj = 0; jj < 4; jj++) {
                wmma::fragment<wmma::matrix_b, 16, 16, 16, __nv_bfloat16, wmma::row_major> bfr;
                wmma::load_matrix_sync(bfr, sX + (k * 16) * TS + wn * 64 + jj * 16, TS);
                #pragma unroll
                for (int i2 = 0; i2 < 2; i2++)
                    wmma::mma_sync(accs[i2][jj], a[i2], bfr, accs[i2][jj]);
            }
        }
        #pragma unroll
        for (int i2 = 0; i2 < 2; i2++)
            #pragma unroll
            for (int jj = 0; jj < 4; jj++) {
                float* p = g_state + sbase + (size_t)(wm * 32 + i2 * 16) * PP + wn * 64 + jj * 16;
                wmma::store_matrix_sync(p, accs[i2][jj], PP, wmma::mem_row_major);
            }
    }
}

// ---------------- SSD pass2: inter-chunk scan (256 blocks) ----------------
__global__ __launch_bounds__(512) void ssd_scan_k() {
    int h = blockIdx.x, b = blockIdx.y, sl = blockIdx.z;
    int tid = threadIdx.x;
    float st[8];
    #pragma unroll
    for (int k = 0; k < 8; k++) st[k] = 0.f;
    for (int c = 0; c < NC; c++) {
        size_t base = (size_t)((b * NC + c) * HH + h) * (NS * PP) + (size_t)sl * 4096;
        float dcy = g_cdecay[(b * NC + c) * HH + h];
        #pragma unroll
        for (int k = 0; k < 8; k++) {
            size_t idx = base + tid + k * 512;
            float loc = g_state[idx];
            g_state[idx] = st[k];
            st[k] = fmaf(dcy, st[k], loc);
        }
    }
}

// ---------------- SSD pass3 (WMMA): y_inter + epilogue ----------------
__global__ __launch_bounds__(256) void ssd_pass3_k(const float* __restrict__ Dv) {
    extern __shared__ char smraw[];
    __nv_bfloat16* sC = (__nv_bfloat16*)smraw;   // 64*TS
    __nv_bfloat16* sS = sC + QQ * TS;            // 128*TS
    float* sY   = (float*)(sS + NS * TS);        // 64*YS
    float* scum = sY + QQ * YS;

    int h = blockIdx.x, c = blockIdx.y, b = blockIdx.z;
    int tid = threadIdx.x;
    int wid = tid >> 5;
    int r0 = b * TSEQ + c * QQ;
    size_t sbase = (size_t)((b * NC + c) * HH + h) * (NS * PP);

    for (int idx = tid; idx < NS * PP; idx += 256)
        sS[(idx >> 7) * TS + (idx & 127)] = __float2bfloat16(g_state[sbase + idx]);
    for (int idx = tid; idx < QQ * NS; idx += 256) {
        int row = idx >> 7, col = idx & 127;
        sC[row * TS + col] =
            __float2bfloat16(g_proj[(size_t)(r0 + row) * WPAD + 2 * DI + HH + NS + col]);
    }
    if (tid < QQ) scum[tid] = g_cum[(size_t)(r0 + tid) * HH + h];
    __syncthreads();

    // y_inter = C @ S  (64x128, k=128)
    {
        int wm = wid >> 1, wn = wid & 1;
        wmma::fragment<wmma::accumulator, 16, 16, 16, float> acc4[4];
        #pragma unroll
        for (int j = 0; j < 4; j++) wmma::fill_fragment(acc4[j], 0.f);
        #pragma unroll
        for (int k = 0; k < 8; k++) {
            wmma::fragment<wmma::matrix_a, 16, 16, 16, __nv_bfloat16, wmma::row_major> a;
            wmma::load_matrix_sync(a, sC + (wm * 16) * TS + k * 16, TS);
            #pragma unroll
            for (int jj = 0; jj < 4; jj++) {
                wmma::fragment<wmma::matrix_b, 16, 16, 16, __nv_bfloat16, wmma::row_major> bfr;
                wmma::load_matrix_sync(bfr, sS + (k * 16) * TS + wn * 64 + jj * 16, TS);
                wmma::mma_sync(acc4[jj], a, bfr, acc4[jj]);
            }
        }
        #pragma unroll
        for (int jj = 0; jj < 4; jj++)
            wmma::store_matrix_sync(sY + (wm * 16) * YS + wn * 64 + jj * 16, acc4[jj],
                                    YS, wmma::mem_row_major);
    }
    __syncthreads();

    // epilogue
    for (int o = tid; o < QQ * PP; o += 256) {
        int i = o >> 7, p = o & 127;
        float yi = expf(scum[i]) * sY[i * YS + p];
        int d = h * PP + p;
        size_t r = (size_t)(r0 + i);
        float act = g_act[r * DI + d];
        float val = g_y[r * DI + d] + yi + Dv[d] * act;
        float gate = g_proj[r * WPAD + d];
        float sg = gate / (1.f + expf(-gate));
        g_yb[r * DI + d] = __float2bfloat16(val * sg);
    }
}

// ---------------- launch ----------------
extern "C" void kernel_launch(void* const* d_in, const int* in_sizes, int n_in,
                              void* d_out, int out_size) {
    const float* x         = (const float*)d_in[0];
    const float* normscale = (const float*)d_in[1];
    const float* w1        = (const float*)d_in[2];
    const float* convw     = (const float*)d_in[3];
    const float* convb     = (const float*)d_in[4];
    const float* A_log     = (const float*)d_in[5];
    const float* dt_bias   = (const float*)d_in[6];
    const float* Dv        = (const float*)d_in[7];
    const float* w2        = (const float*)d_in[8];
    float* out             = (float*)d_out;

    void *p_h, *p_w1, *p_w2, *p_proj, *p_yb;
    cudaGetSymbolAddress(&p_h, g_h);
    cudaGetSymbolAddress(&p_w1, g_w1);
    cudaGetSymbolAddress(&p_w2, g_w2);
    cudaGetSymbolAddress(&p_proj, g_proj);
    cudaGetSymbolAddress(&p_yb, g_yb);

    const int smem1 = (4 * QQ * TS + QQ * MS) * 2 + (QQ * MS + 3 * QQ) * 4;
    const int smem3 = (QQ * TS + NS * TS) * 2 + (QQ * YS + QQ) * 4;
    cudaFuncSetAttribute(ssd_pass1_k, cudaFuncAttributeMaxDynamicSharedMemorySize, smem1);
    cudaFuncSetAttribute(ssd_pass3_k, cudaFuncAttributeMaxDynamicSharedMemorySize, smem3);

    {
        size_t n1 = (size_t)E * WPAD;
        conv_w1_k<<<(unsigned)((n1 + 255) / 256), 256>>>(w1);
        size_t n2 = (size_t)DI * E;
        conv_w2_k<<<(unsigned)((n2 + 255) / 256), 256>>>(w2);
    }
    rmsnorm_k<<<R_TOT, 256>>>(x, normscale);
    {
        dim3 grid(WPAD / 128, R_TOT / 128);
        gemm_bf16<<<grid, 256>>>((const __nv_bfloat16*)p_h, (const __nv_bfloat16*)p_w1,
                                 (float*)p_proj, nullptr,
                                 R_TOT, WPAD, E, E, WPAD, WPAD, 0);
    }
    {
        size_t n = (size_t)R_TOT * DI;
        conv_silu_k<<<(unsigned)((n + 255) / 256), 256>>>(convw, convb);
    }
    {
        dim3 grid(HH, NC, BATCH);
        ssd_pass1_k<<<grid, 256, smem1>>>(A_log, dt_bias);
    }
    {
        dim3 grid(HH, BATCH, 4);
        ssd_scan_k<<<grid, 512>>>();
    }
    {
        dim3 grid(HH, NC, BATCH);
        ssd_pass3_k<<<grid, 256, smem3>>>(Dv);
    }
    {
        dim3 grid(E / 128, R_TOT / 128);
        gemm_bf16<<<grid, 256>>>((const __nv_bfloat16*)p_yb, (const __nv_bfloat16*)p_w2,
                                 out, x,
                                 R_TOT, E, DI, DI, E, E, 1);
    }
}

// round 10
// speedup vs baseline: 1.8227x; 1.0327x over previous
#include <cstdint>
#include <cuda_runtime.h>
#include <cuda_bf16.h>
#include <mma.h>
#include <math.h>

using namespace nvcuda;

// ---------------- problem constants ----------------
#define BATCH   2
#define TSEQ    2048
#define R_TOT   4096
#define E       2048
#define DI      4096
#define HH      32
#define PP      128
#define NS      128
#define QQ      64
#define NC      32
#define PROJW   8480
#define WPAD    8576          // padded to multiple of 128
#define DCONV   4

#define TS      136      // bf16 tile stride
#define MS      72       // M tile stride
#define YS      132      // fp32 y tile stride

// GEMM tiling
#define GBK     64
#define SA_STR  72       // A smem stride (GBK + 8)
#define SB_STR  136      // B smem stride (128 + 8)
#define CY_STR  132      // fp32 staging stride

// ---------------- scratch ----------------
__device__ __nv_bfloat16 g_h[(size_t)R_TOT * E];
__device__ __nv_bfloat16 g_w1[(size_t)E * WPAD];
__device__ __nv_bfloat16 g_w2[(size_t)DI * E];
__device__ __nv_bfloat16 g_proj[(size_t)R_TOT * WPAD];
__device__ __nv_bfloat16 g_act[(size_t)R_TOT * DI];
__device__ float         g_y[(size_t)R_TOT * DI];
__device__ __nv_bfloat16 g_yb[(size_t)R_TOT * DI];
__device__ float         g_state[(size_t)BATCH * NC * HH * NS * PP];
__device__ float         g_cdecay[BATCH * NC * HH];
__device__ float         g_cum[(size_t)R_TOT * HH];

// ---------------- cp.async helpers ----------------
__device__ __forceinline__ void cpa16(void* dst, const void* src) {
    unsigned int d = (unsigned int)__cvta_generic_to_shared(dst);
    asm volatile("cp.async.cg.shared.global [%0], [%1], 16;\n" :: "r"(d), "l"(src));
}
#define CP_COMMIT() asm volatile("cp.async.commit_group;\n" ::: "memory")
#define CP_WAIT0()  asm volatile("cp.async.wait_group 0;\n" ::: "memory")

// ---------------- weight conversion (fp32 -> bf16) ----------------
__global__ void conv_w1_k(const float* __restrict__ w) {
    size_t idx = (size_t)blockIdx.x * 256 + threadIdx.x;
    if (idx >= (size_t)E * WPAD) return;
    int row = (int)(idx / WPAD);
    int col = (int)(idx % WPAD);
    float v = (col < PROJW) ? w[(size_t)row * PROJW + col] : 0.f;
    g_w1[idx] = __float2bfloat16(v);
}
__global__ void conv_w2_k(const float* __restrict__ w) {
    size_t idx = (size_t)blockIdx.x * 256 + threadIdx.x;
    if (idx >= (size_t)DI * E) return;
    g_w2[idx] = __float2bfloat16(w[idx]);
}

// ---------------- rmsnorm ----------------
__global__ void rmsnorm_k(const float* __restrict__ x, const float* __restrict__ scale) {
    int r = blockIdx.x;
    int tid = threadIdx.x;
    const float* xr = x + (size_t)r * E;
    __shared__ float red[256];
    float ss = 0.f;
    for (int i = tid; i < E; i += 256) { float v = xr[i]; ss += v * v; }
    red[tid] = ss; __syncthreads();
    for (int s = 128; s > 0; s >>= 1) {
        if (tid < s) red[tid] += red[tid + s];
        __syncthreads();
    }
    float rstd = rsqrtf(red[0] / (float)E + 1e-6f);
    for (int i = tid; i < E; i += 256)
        g_h[(size_t)r * E + i] = __float2bfloat16(xr[i] * rstd * scale[i]);
}

// ---------------- bf16 WMMA GEMM, BK=64, 2-stage cp.async ----------------
// C = A @ B (+ res). A:[M,K] bf16, B:[K,N] bf16 row-major.
// MODE 0: store bf16 (staged through smem). MODE 1: store fp32 + residual.
template<int MODE>
__global__ __launch_bounds__(256) void gemm_bf16(
    const __nv_bfloat16* __restrict__ A, const __nv_bfloat16* __restrict__ Bw,
    void* __restrict__ Cout, const float* __restrict__ res,
    int K, int lda, int ldb, int ldc)
{
    extern __shared__ char smraw[];
    __nv_bfloat16* sA[2];
    __nv_bfloat16* sB[2];
    sA[0] = (__nv_bfloat16*)smraw;                       // 128*72
    sB[0] = sA[0] + 128 * SA_STR;                        // 64*136
    sA[1] = sB[0] + GBK * SB_STR;
    sB[1] = sA[1] + 128 * SA_STR;

    int tid = threadIdx.x;
    int wid = tid >> 5;
    int warp_m = wid >> 2;
    int warp_n = wid & 3;
    int row0 = blockIdx.y * 128;
    int col0 = blockIdx.x * 128;

    wmma::fragment<wmma::accumulator, 16, 16, 16, float> acc[4][2];
    if (MODE == 1) {
        #pragma unroll
        for (int i = 0; i < 4; i++)
            #pragma unroll
            for (int j = 0; j < 2; j++) {
                const float* p = res + (size_t)(row0 + warp_m * 64 + i * 16) * ldc
                                     + col0 + warp_n * 32 + j * 16;
                wmma::load_matrix_sync(acc[i][j], p, ldc, wmma::mem_row_major);
            }
    } else {
        #pragma unroll
        for (int i = 0; i < 4; i++)
            #pragma unroll
            for (int j = 0; j < 2; j++)
                wmma::fill_fragment(acc[i][j], 0.f);
    }

    // prologue: stage 0
    {
        #pragma unroll
        for (int it = 0; it < 4; it++) {
            int u = tid + it * 256;
            int r = u >> 3, c = (u & 7) * 8;
            cpa16(sA[0] + r * SA_STR + c, A + (size_t)(row0 + r) * lda + c);
        }
        #pragma unroll
        for (int it = 0; it < 4; it++) {
            int u = tid + it * 256;
            int r = u >> 4, c = (u & 15) * 8;
            cpa16(sB[0] + r * SB_STR + c, Bw + (size_t)r * ldb + col0 + c);
        }
        CP_COMMIT();
    }

    int nst = K / GBK;
    for (int s2 = 0; s2 < nst; s2++) {
        int buf = s2 & 1;
        CP_WAIT0();
        __syncthreads();
        if (s2 + 1 < nst) {
            int kn = (s2 + 1) * GBK;
            int nb = buf ^ 1;
            #pragma unroll
            for (int it = 0; it < 4; it++) {
                int u = tid + it * 256;
                int r = u >> 3, c = (u & 7) * 8;
                cpa16(sA[nb] + r * SA_STR + c, A + (size_t)(row0 + r) * lda + kn + c);
            }
            #pragma unroll
            for (int it = 0; it < 4; it++) {
                int u = tid + it * 256;
                int r = u >> 4, c = (u & 15) * 8;
                cpa16(sB[nb] + r * SB_STR + c, Bw + (size_t)(kn + r) * ldb + col0 + c);
            }
            CP_COMMIT();
        }
        #pragma unroll
        for (int kk = 0; kk < GBK; kk += 16) {
            wmma::fragment<wmma::matrix_a, 16, 16, 16, __nv_bfloat16, wmma::row_major> af[4];
            wmma::fragment<wmma::matrix_b, 16, 16, 16, __nv_bfloat16, wmma::row_major> bf[2];
            #pragma unroll
            for (int i = 0; i < 4; i++)
                wmma::load_matrix_sync(af[i], sA[buf] + (warp_m * 64 + i * 16) * SA_STR + kk, SA_STR);
            #pragma unroll
            for (int j = 0; j < 2; j++)
                wmma::load_matrix_sync(bf[j], sB[buf] + kk * SB_STR + warp_n * 32 + j * 16, SB_STR);
            #pragma unroll
            for (int i = 0; i < 4; i++)
                #pragma unroll
                for (int j = 0; j < 2; j++)
                    wmma::mma_sync(acc[i][j], af[i], bf[j], acc[i][j]);
        }
        __syncthreads();
    }

    if (MODE == 1) {
        float* out = (float*)Cout;
        #pragma unroll
        for (int i = 0; i < 4; i++)
            #pragma unroll
            for (int j = 0; j < 2; j++) {
                float* p = out + (size_t)(row0 + warp_m * 64 + i * 16) * ldc
                               + col0 + warp_n * 32 + j * 16;
                wmma::store_matrix_sync(p, acc[i][j], ldc, wmma::mem_row_major);
            }
    } else {
        // stage fp32 -> smem, convert -> bf16, vectorized store
        float* sY = (float*)smraw;   // 128*132 fp32 = 67584 B
        #pragma unroll
        for (int i = 0; i < 4; i++)
            #pragma unroll
            for (int j = 0; j < 2; j++)
                wmma::store_matrix_sync(sY + (warp_m * 64 + i * 16) * CY_STR
                                           + warp_n * 32 + j * 16,
                                        acc[i][j], CY_STR, wmma::mem_row_major);
        __syncthreads();
        __nv_bfloat16* out = (__nv_bfloat16*)Cout;
        #pragma unroll
        for (int it = 0; it < 8; it++) {
            int u = tid + it * 256;
            int r = u >> 4, c = (u & 15) * 8;
            const float* sp = sY + r * CY_STR + c;
            uint4 v;
            unsigned int* vp = (unsigned int*)&v;
            #pragma unroll
            for (int q = 0; q < 4; q++) {
                unsigned int lo = (unsigned int)__bfloat16_as_ushort(__float2bfloat16(sp[q * 2]));
                unsigned int hi = (unsigned int)__bfloat16_as_ushort(__float2bfloat16(sp[q * 2 + 1]));
                vp[q] = lo | (hi << 16);
            }
            *(uint4*)(out + (size_t)(row0 + r) * ldc + col0 + c) = v;
        }
    }
}

// ---------------- conv + silu (vectorized, bf16 in/out) ----------------
__global__ void conv_silu_k(const float* __restrict__ cw, const float* __restrict__ cb) {
    size_t idx = (size_t)blockIdx.x * 256 + threadIdx.x;       // one per 8 channels
    if (idx >= (size_t)R_TOT * DI / 8) return;
    int e0 = (int)((idx * 8) & (DI - 1));
    int r  = (int)(idx >> 9);                                   // idx*8 >> 12
    int t  = r & (TSEQ - 1);

    float acc[8];
    const float4* cbp = (const float4*)(cb + e0);
    float4 cb0 = cbp[0], cb1 = cbp[1];
    acc[0] = cb0.x; acc[1] = cb0.y; acc[2] = cb0.z; acc[3] = cb0.w;
    acc[4] = cb1.x; acc[5] = cb1.y; acc[6] = cb1.z; acc[7] = cb1.w;

    #pragma unroll
    for (int k = 0; k < DCONV; k++) {
        int tt = t - 3 + k;
        if (tt >= 0) {
            uint4 pv = *(const uint4*)(g_proj + (size_t)(r - 3 + k) * WPAD + DI + e0);
            const float4* wp = (const float4*)(cw + k * DI + e0);
            float4 w0 = wp[0], w1 = wp[1];
            const unsigned int* pu = (const unsigned int*)&pv;
            float wv[8] = {w0.x, w0.y, w0.z, w0.w, w1.x, w1.y, w1.z, w1.w};
            #pragma unroll
            for (int q = 0; q < 4; q++) {
                float lo = __bfloat162float(__ushort_as_bfloat16((unsigned short)(pu[q] & 0xFFFF)));
                float hi = __bfloat162float(__ushort_as_bfloat16((unsigned short)(pu[q] >> 16)));
                acc[q * 2]     += lo * wv[q * 2];
                acc[q * 2 + 1] += hi * wv[q * 2 + 1];
            }
        }
    }
    uint4 ov;
    unsigned int* op = (unsigned int*)&ov;
    #pragma unroll
    for (int q = 0; q < 4; q++) {
        float a0 = acc[q * 2],     s0 = a0 / (1.f + expf(-a0));
        float a1 = acc[q * 2 + 1], s1 = a1 / (1.f + expf(-a1));
        unsigned int lo = (unsigned int)__bfloat16_as_ushort(__float2bfloat16(s0));
        unsigned int hi = (unsigned int)__bfloat16_as_ushort(__float2bfloat16(s1));
        op[q] = lo | (hi << 16);
    }
    *(uint4*)(g_act + idx * 8) = ov;
}

// ---------------- SSD pass1 (WMMA) ----------------
__global__ __launch_bounds__(256) void ssd_pass1_k(
    const float* __restrict__ A_log, const float* __restrict__ dt_bias)
{
    extern __shared__ char smraw[];
    __nv_bfloat16* sB  = (__nv_bfloat16*)smraw;
    __nv_bfloat16* sC  = sB + QQ * TS;
    __nv_bfloat16* sX  = sC + QQ * TS;
    __nv_bfloat16* sWB = sX + QQ * TS;
    __nv_bfloat16* sMb = sWB + QQ * TS;
    float* sMf  = (float*)(sMb + QQ * MS);
    float* sdt  = sMf + QQ * MS;
    float* scum = sdt + QQ;
    float* sw   = scum + QQ;

    int h = blockIdx.x, c = blockIdx.y, b = blockIdx.z;
    int tid = threadIdx.x;
    int wid = tid >> 5;
    int r0 = b * TSEQ + c * QQ;

    if (tid < QQ) {
        float d = __bfloat162float(g_proj[(size_t)(r0 + tid) * WPAD + 2 * DI + h]) + dt_bias[h];
        float dt = (d > 20.f) ? d : log1pf(expf(d));
        sdt[tid] = dt;
        scum[tid] = -expf(A_log[h]) * dt;
    }
    __syncthreads();
    for (int off = 1; off < QQ; off <<= 1) {
        float add = 0.f;
        if (tid < QQ && tid >= off) add = scum[tid - off];
        __syncthreads();
        if (tid < QQ) scum[tid] += add;
        __syncthreads();
    }
    if (tid < QQ) {
        g_cum[(size_t)(r0 + tid) * HH + h] = scum[tid];
        float clast = scum[QQ - 1];
        sw[tid] = expf(clast - scum[tid]) * sdt[tid];
        if (tid == 0) g_cdecay[(b * NC + c) * HH + h] = expf(clast);
    }
    __syncthreads();

    for (int idx = tid; idx < QQ * NS; idx += 256) {
        int row = idx >> 7, col = idx & 127;
        size_t pb = (size_t)(r0 + row) * WPAD;
        __nv_bfloat16 bv = g_proj[pb + 2 * DI + HH + col];
        sB[row * TS + col]  = bv;
        sC[row * TS + col]  = g_proj[pb + 2 * DI + HH + NS + col];
        sX[row * TS + col]  = g_act[(size_t)(r0 + row) * DI + h * PP + col];
        sWB[row * TS + col] = __float2bfloat16(__bfloat162float(bv) * sw[row]);
    }
    __syncthreads();

    // CB = C @ B^T
    {
        int wm = wid >> 1, wn = wid & 1;
        wmma::fragment<wmma::accumulator, 16, 16, 16, float> acc2[2];
        wmma::fill_fragment(acc2[0], 0.f);
        wmma::fill_fragment(acc2[1], 0.f);
        #pragma unroll
        for (int k = 0; k < 8; k++) {
            wmma::fragment<wmma::matrix_a, 16, 16, 16, __nv_bfloat16, wmma::row_major> a;
            wmma::load_matrix_sync(a, sC + (wm * 16) * TS + k * 16, TS);
            #pragma unroll
            for (int j2 = 0; j2 < 2; j2++) {
                wmma::fragment<wmma::matrix_b, 16, 16, 16, __nv_bfloat16, wmma::col_major> bfr;
                wmma::load_matrix_sync(bfr, sB + (wn * 32 + j2 * 16) * TS + k * 16, TS);
                wmma::mma_sync(acc2[j2], a, bfr, acc2[j2]);
            }
        }
        #pragma unroll
        for (int j2 = 0; j2 < 2; j2++)
            wmma::store_matrix_sync(sMf + (wm * 16) * MS + wn * 32 + j2 * 16, acc2[j2],
                                    MS, wmma::mem_row_major);
    }
    __syncthreads();

    for (int e = tid; e < QQ * QQ; e += 256) {
        int i = e >> 6, j = e & 63;
        float m = 0.f;
        if (j <= i)
            m = sMf[i * MS + j] * expf(scum[i] - scum[j]) * sdt[j];
        sMb[i * MS + j] = __float2bfloat16(m);
    }
    __syncthreads();

    // y_intra = M @ X
    {
        int wm = wid >> 1, wn = wid & 1;
        wmma::fragment<wmma::accumulator, 16, 16, 16, float> acc4[4];
        #pragma unroll
        for (int j = 0; j < 4; j++) wmma::fill_fragment(acc4[j], 0.f);
        #pragma unroll
        for (int k = 0; k < 4; k++) {
            wmma::fragment<wmma::matrix_a, 16, 16, 16, __nv_bfloat16, wmma::row_major> a;
            wmma::load_matrix_sync(a, sMb + (wm * 16) * MS + k * 16, MS);
            #pragma unroll
            for (int jj = 0; jj < 4; jj++) {
                wmma::fragment<wmma::matrix_b, 16, 16, 16, __nv_bfloat16, wmma::row_major> bfr;
                wmma::load_matrix_sync(bfr, sX + (k * 16) * TS + wn * 64 + jj * 16, TS);
                wmma::mma_sync(acc4[jj], a, bfr, acc4[jj]);
            }
        }
        #pragma unroll
        for (int jj = 0; jj < 4; jj++) {
            float* p = g_y + (size_t)(r0 + wm * 16) * DI + h * PP + wn * 64 + jj * 16;
            wmma::store_matrix_sync(p, acc4[jj], DI, wmma::mem_row_major);
        }
    }

    // state = WB^T @ X
    {
        int wm = wid >> 1, wn = wid & 1;
        size_t sbase = (size_t)((b * NC + c) * HH + h) * (NS * PP);
        wmma::fragment<wmma::accumulator, 16, 16, 16, float> accs[2][4];
        #pragma unroll
        for (int i2 = 0; i2 < 2; i2++)
            #pragma unroll
            for (int jj = 0; jj < 4; jj++) wmma::fill_fragment(accs[i2][jj], 0.f);
        #pragma unroll
        for (int k = 0; k < 4; k++) {
            wmma::fragment<wmma::matrix_a, 16, 16, 16, __nv_bfloat16, wmma::col_major> a[2];
            #pragma unroll
            for (int i2 = 0; i2 < 2; i2++)
                wmma::load_matrix_sync(a[i2], sWB + (k * 16) * TS + wm * 32 + i2 * 16, TS);
            #pragma unroll
            for (int jj = 0; jj < 4; jj++) {
                wmma::fragment<wmma::matrix_b, 16, 16, 16, __nv_bfloat16, wmma::row_major> bfr;
                wmma::load_matrix_sync(bfr, sX + (k * 16) * TS + wn * 64 + jj * 16, TS);
                #pragma unroll
                for (int i2 = 0; i2 < 2; i2++)
                    wmma::mma_sync(accs[i2][jj], a[i2], bfr, accs[i2][jj]);
            }
        }
        #pragma unroll
        for (int i2 = 0; i2 < 2; i2++)
            #pragma unroll
            for (int jj = 0; jj < 4; jj++) {
                float* p = g_state + sbase + (size_t)(wm * 32 + i2 * 16) * PP + wn * 64 + jj * 16;
                wmma::store_matrix_sync(p, accs[i2][jj], PP, wmma::mem_row_major);
            }
    }
}

// ---------------- SSD pass2: inter-chunk scan ----------------
__global__ __launch_bounds__(512) void ssd_scan_k() {
    int h = blockIdx.x, b = blockIdx.y, sl = blockIdx.z;
    int tid = threadIdx.x;
    float st[8];
    #pragma unroll
    for (int k = 0; k < 8; k++) st[k] = 0.f;
    for (int c = 0; c < NC; c++) {
        size_t base = (size_t)((b * NC + c) * HH + h) * (NS * PP) + (size_t)sl * 4096;
        float dcy = g_cdecay[(b * NC + c) * HH + h];
        #pragma unroll
        for (int k = 0; k < 8; k++) {
            size_t idx = base + tid + k * 512;
            float loc = g_state[idx];
            g_state[idx] = st[k];
            st[k] = fmaf(dcy, st[k], loc);
        }
    }
}

// ---------------- SSD pass3 (WMMA) ----------------
__global__ __launch_bounds__(256) void ssd_pass3_k(const float* __restrict__ Dv) {
    extern __shared__ char smraw[];
    __nv_bfloat16* sC = (__nv_bfloat16*)smraw;
    __nv_bfloat16* sS = sC + QQ * TS;
    float* sY   = (float*)(sS + NS * TS);
    float* scum = sY + QQ * YS;

    int h = blockIdx.x, c = blockIdx.y, b = blockIdx.z;
    int tid = threadIdx.x;
    int wid = tid >> 5;
    int r0 = b * TSEQ + c * QQ;
    size_t sbase = (size_t)((b * NC + c) * HH + h) * (NS * PP);

    for (int idx = tid; idx < NS * PP; idx += 256)
        sS[(idx >> 7) * TS + (idx & 127)] = __float2bfloat16(g_state[sbase + idx]);
    for (int idx = tid; idx < QQ * NS; idx += 256) {
        int row = idx >> 7, col = idx & 127;
        sC[row * TS + col] = g_proj[(size_t)(r0 + row) * WPAD + 2 * DI + HH + NS + col];
    }
    if (tid < QQ) scum[tid] = g_cum[(size_t)(r0 + tid) * HH + h];
    __syncthreads();

    {
        int wm = wid >> 1, wn = wid & 1;
        wmma::fragment<wmma::accumulator, 16, 16, 16, float> acc4[4];
        #pragma unroll
        for (int j = 0; j < 4; j++) wmma::fill_fragment(acc4[j], 0.f);
        #pragma unroll
        for (int k = 0; k < 8; k++) {
            wmma::fragment<wmma::matrix_a, 16, 16, 16, __nv_bfloat16, wmma::row_major> a;
            wmma::load_matrix_sync(a, sC + (wm * 16) * TS + k * 16, TS);
            #pragma unroll
            for (int jj = 0; jj < 4; jj++) {
                wmma::fragment<wmma::matrix_b, 16, 16, 16, __nv_bfloat16, wmma::row_major> bfr;
                wmma::load_matrix_sync(bfr, sS + (k * 16) * TS + wn * 64 + jj * 16, TS);
                wmma::mma_sync(acc4[jj], a, bfr, acc4[jj]);
            }
        }
        #pragma unroll
        for (int jj = 0; jj < 4; jj++)
            wmma::store_matrix_sync(sY + (wm * 16) * YS + wn * 64 + jj * 16, acc4[jj],
                                    YS, wmma::mem_row_major);
    }
    __syncthreads();

    for (int o = tid; o < QQ * PP; o += 256) {
        int i = o >> 7, p = o & 127;
        float yi = expf(scum[i]) * sY[i * YS + p];
        int d = h * PP + p;
        size_t r = (size_t)(r0 + i);
        float act = __bfloat162float(g_act[r * DI + d]);
        float val = g_y[r * DI + d] + yi + Dv[d] * act;
        float gate = __bfloat162float(g_proj[r * WPAD + d]);
        float sg = gate / (1.f + expf(-gate));
        g_yb[r * DI + d] = __float2bfloat16(val * sg);
    }
}

// ---------------- launch ----------------
extern "C" void kernel_launch(void* const* d_in, const int* in_sizes, int n_in,
                              void* d_out, int out_size) {
    const float* x         = (const float*)d_in[0];
    const float* normscale = (const float*)d_in[1];
    const float* w1        = (const float*)d_in[2];
    const float* convw     = (const float*)d_in[3];
    const float* convb     = (const float*)d_in[4];
    const float* A_log     = (const float*)d_in[5];
    const float* dt_bias   = (const float*)d_in[6];
    const float* Dv        = (const float*)d_in[7];
    const float* w2        = (const float*)d_in[8];
    float* out             = (float*)d_out;

    void *p_h, *p_w1, *p_w2, *p_proj, *p_yb;
    cudaGetSymbolAddress(&p_h, g_h);
    cudaGetSymbolAddress(&p_w1, g_w1);
    cudaGetSymbolAddress(&p_w2, g_w2);
    cudaGetSymbolAddress(&p_proj, g_proj);
    cudaGetSymbolAddress(&p_yb, g_yb);

    const int smemG = 2 * (128 * SA_STR + GBK * SB_STR) * 2;     // 71680
    const int smem1 = (4 * QQ * TS + QQ * MS) * 2 + (QQ * MS + 3 * QQ) * 4;
    const int smem3 = (QQ * TS + NS * TS) * 2 + (QQ * YS + QQ) * 4;
    cudaFuncSetAttribute(gemm_bf16<0>, cudaFuncAttributeMaxDynamicSharedMemorySize, smemG);
    cudaFuncSetAttribute(gemm_bf16<1>, cudaFuncAttributeMaxDynamicSharedMemorySize, smemG);
    cudaFuncSetAttribute(ssd_pass1_k, cudaFuncAttributeMaxDynamicSharedMemorySize, smem1);
    cudaFuncSetAttribute(ssd_pass3_k, cudaFuncAttributeMaxDynamicSharedMemorySize, smem3);

    {
        size_t n1 = (size_t)E * WPAD;
        conv_w1_k<<<(unsigned)((n1 + 255) / 256), 256>>>(w1);
        size_t n2 = (size_t)DI * E;
        conv_w2_k<<<(unsigned)((n2 + 255) / 256), 256>>>(w2);
    }
    rmsnorm_k<<<R_TOT, 256>>>(x, normscale);
    {
        dim3 grid(WPAD / 128, R_TOT / 128);
        gemm_bf16<0><<<grid, 256, smemG>>>((const __nv_bfloat16*)p_h,
                                           (const __nv_bfloat16*)p_w1,
                                           p_proj, nullptr, E, E, WPAD, WPAD);
    }
    {
        size_t n = (size_t)R_TOT * DI / 8;
        conv_silu_k<<<(unsigned)((n + 255) / 256), 256>>>(convw, convb);
    }
    {
        dim3 grid(HH, NC, BATCH);
        ssd_pass1_k<<<grid, 256, smem1>>>(A_log, dt_bias);
    }
    {
        dim3 grid(HH, BATCH, 4);
        ssd_scan_k<<<grid, 512>>>();
    }
    {
        dim3 grid(HH, NC, BATCH);
        ssd_pass3_k<<<grid, 256, smem3>>>(Dv);
    }
    {
        dim3 grid(E / 128, R_TOT / 128);
        gemm_bf16<1><<<grid, 256, smemG>>>((const __nv_bfloat16*)p_yb,
                                           (const __nv_bfloat16*)p_w2,
                                           out, x, DI, DI, E, E);
    }
}

// round 14
// speedup vs baseline: 2.0956x; 1.1498x over previous
#include <cstdint>
#include <cuda_runtime.h>
#include <cuda_bf16.h>
#include <mma.h>
#include <math.h>

using namespace nvcuda;

// ---------------- problem constants ----------------
#define BATCH   2
#define TSEQ    2048
#define R_TOT   4096
#define E       2048
#define DI      4096
#define HH      32
#define PP      128
#define NS      128
#define QQ      64
#define NC      32
#define PROJW   8480
#define WPAD    8704          // padded to multiple of 256 (GEMM N-tile)
#define DCONV   4

#define TS      136      // bf16 tile stride
#define MS      72       // M tile stride
#define YS      132      // fp32 y tile stride

// GEMM tiling: CTA 128x256, warp 64x64, BK=64, 2 stages
#define GBK     64
#define SA_STR  72       // A smem stride (64 + 8)
#define SB_STR  264      // B smem stride (256 + 8)
#define CY_STR  264      // fp32 staging stride (epilogue)
#define ST_STR  132      // fp32 staging stride (pass1 state)

// ---------------- scratch ----------------
__device__ __nv_bfloat16 g_h[(size_t)R_TOT * E];
__device__ __nv_bfloat16 g_w1[(size_t)E * WPAD];
__device__ __nv_bfloat16 g_w2[(size_t)DI * E];
__device__ __nv_bfloat16 g_proj[(size_t)R_TOT * WPAD];
__device__ __nv_bfloat16 g_act[(size_t)R_TOT * DI];
__device__ float         g_y[(size_t)R_TOT * DI];
__device__ __nv_bfloat16 g_yb[(size_t)R_TOT * DI];
__device__ __nv_bfloat16 g_state[(size_t)BATCH * NC * HH * NS * PP];
__device__ float         g_cdecay[BATCH * NC * HH];
__device__ float         g_cum[(size_t)R_TOT * HH];

// ---------------- cp.async helpers ----------------
__device__ __forceinline__ void cpa16(void* dst, const void* src) {
    unsigned int d = (unsigned int)__cvta_generic_to_shared(dst);
    asm volatile("cp.async.cg.shared.global [%0], [%1], 16;\n" :: "r"(d), "l"(src));
}
#define CP_COMMIT() asm volatile("cp.async.commit_group;\n" ::: "memory")
#define CP_WAIT0()  asm volatile("cp.async.wait_group 0;\n" ::: "memory")

// ---------------- weight conversion (fp32 -> bf16) ----------------
__global__ void conv_w1_k(const float* __restrict__ w) {
    size_t idx = (size_t)blockIdx.x * 256 + threadIdx.x;
    if (idx >= (size_t)E * WPAD) return;
    int row = (int)(idx / WPAD);
    int col = (int)(idx % WPAD);
    float v = (col < PROJW) ? w[(size_t)row * PROJW + col] : 0.f;
    g_w1[idx] = __float2bfloat16(v);
}
__global__ void conv_w2_k(const float* __restrict__ w) {
    size_t idx = (size_t)blockIdx.x * 256 + threadIdx.x;
    if (idx >= (size_t)DI * E) return;
    g_w2[idx] = __float2bfloat16(w[idx]);
}

// ---------------- rmsnorm ----------------
__global__ void rmsnorm_k(const float* __restrict__ x, const float* __restrict__ scale) {
    int r = blockIdx.x;
    int tid = threadIdx.x;
    const float* xr = x + (size_t)r * E;
    __shared__ float red[256];
    float ss = 0.f;
    for (int i = tid; i < E; i += 256) { float v = xr[i]; ss += v * v; }
    red[tid] = ss; __syncthreads();
    for (int s = 128; s > 0; s >>= 1) {
        if (tid < s) red[tid] += red[tid + s];
        __syncthreads();
    }
    float rstd = rsqrtf(red[0] / (float)E + 1e-6f);
    for (int i = tid; i < E; i += 256)
        g_h[(size_t)r * E + i] = __float2bfloat16(xr[i] * rstd * scale[i]);
}

// ---------------- bf16 WMMA GEMM, CTA 128x256, warp 64x64, BK=64 ----------------
// C = A @ B (+ res). A:[M,K] bf16, B:[K,N] bf16 row-major.
// MODE 0: store bf16 (staged through smem). MODE 1: store fp32 + residual.
template<int MODE>
__global__ __launch_bounds__(256, 1) void gemm_bf16(
    const __nv_bfloat16* __restrict__ A, const __nv_bfloat16* __restrict__ Bw,
    void* __restrict__ Cout, const float* __restrict__ res,
    int K, int lda, int ldb, int ldc)
{
    extern __shared__ char smraw[];
    __nv_bfloat16* sA[2];
    __nv_bfloat16* sB[2];
    sA[0] = (__nv_bfloat16*)smraw;                       // 128*72
    sB[0] = sA[0] + 128 * SA_STR;                        // 64*264
    sA[1] = sB[0] + GBK * SB_STR;
    sB[1] = sA[1] + 128 * SA_STR;

    int tid = threadIdx.x;
    int wid = tid >> 5;
    int warp_m = wid >> 2;   // 0..1 -> 64 rows
    int warp_n = wid & 3;    // 0..3 -> 64 cols
    int row0 = blockIdx.y * 128;
    int col0 = blockIdx.x * 256;

    wmma::fragment<wmma::accumulator, 16, 16, 16, float> acc[4][4];
    if (MODE == 1) {
        #pragma unroll
        for (int i = 0; i < 4; i++)
            #pragma unroll
            for (int j = 0; j < 4; j++) {
                const float* p = res + (size_t)(row0 + warp_m * 64 + i * 16) * ldc
                                     + col0 + warp_n * 64 + j * 16;
                wmma::load_matrix_sync(acc[i][j], p, ldc, wmma::mem_row_major);
            }
    } else {
        #pragma unroll
        for (int i = 0; i < 4; i++)
            #pragma unroll
            for (int j = 0; j < 4; j++)
                wmma::fill_fragment(acc[i][j], 0.f);
    }

    // prologue: stage 0
    {
        #pragma unroll
        for (int it = 0; it < 4; it++) {
            int u = tid + it * 256;
            int r = u >> 3, c = (u & 7) * 8;
            cpa16(sA[0] + r * SA_STR + c, A + (size_t)(row0 + r) * lda + c);
        }
        #pragma unroll
        for (int it = 0; it < 8; it++) {
            int u = tid + it * 256;
            int r = u >> 5, c = (u & 31) * 8;
            cpa16(sB[0] + r * SB_STR + c, Bw + (size_t)r * ldb + col0 + c);
        }
        CP_COMMIT();
    }

    int nst = K / GBK;
    for (int s2 = 0; s2 < nst; s2++) {
        int buf = s2 & 1;
        CP_WAIT0();
        __syncthreads();
        if (s2 + 1 < nst) {
            int kn = (s2 + 1) * GBK;
            int nb = buf ^ 1;
            #pragma unroll
            for (int it = 0; it < 4; it++) {
                int u = tid + it * 256;
                int r = u >> 3, c = (u & 7) * 8;
                cpa16(sA[nb] + r * SA_STR + c, A + (size_t)(row0 + r) * lda + kn + c);
            }
            #pragma unroll
            for (int it = 0; it < 8; it++) {
                int u = tid + it * 256;
                int r = u >> 5, c = (u & 31) * 8;
                cpa16(sB[nb] + r * SB_STR + c, Bw + (size_t)(kn + r) * ldb + col0 + c);
            }
            CP_COMMIT();
        }
        #pragma unroll
        for (int kk = 0; kk < GBK; kk += 16) {
            wmma::fragment<wmma::matrix_a, 16, 16, 16, __nv_bfloat16, wmma::row_major> af[4];
            #pragma unroll
            for (int i = 0; i < 4; i++)
                wmma::load_matrix_sync(af[i], sA[buf] + (warp_m * 64 + i * 16) * SA_STR + kk, SA_STR);
            #pragma unroll
            for (int j = 0; j < 4; j++) {
                wmma::fragment<wmma::matrix_b, 16, 16, 16, __nv_bfloat16, wmma::row_major> bf;
                wmma::load_matrix_sync(bf, sB[buf] + kk * SB_STR + warp_n * 64 + j * 16, SB_STR);
                #pragma unroll
                for (int i = 0; i < 4; i++)
                    wmma::mma_sync(acc[i][j], af[i], bf, acc[i][j]);
            }
        }
        __syncthreads();
    }

    if (MODE == 1) {
        float* out = (float*)Cout;
        #pragma unroll
        for (int i = 0; i < 4; i++)
            #pragma unroll
            for (int j = 0; j < 4; j++) {
                float* p = out + (size_t)(row0 + warp_m * 64 + i * 16) * ldc
                               + col0 + warp_n * 64 + j * 16;
                wmma::store_matrix_sync(p, acc[i][j], ldc, wmma::mem_row_major);
            }
    } else {
        // stage fp32 -> smem, convert -> bf16, vectorized store
        float* sY = (float*)smraw;   // 128*264 fp32 = 135168 B
        #pragma unroll
        for (int i = 0; i < 4; i++)
            #pragma unroll
            for (int j = 0; j < 4; j++)
                wmma::store_matrix_sync(sY + (warp_m * 64 + i * 16) * CY_STR
                                           + warp_n * 64 + j * 16,
                                        acc[i][j], CY_STR, wmma::mem_row_major);
        __syncthreads();
        __nv_bfloat16* out = (__nv_bfloat16*)Cout;
        #pragma unroll
        for (int it = 0; it < 16; it++) {
            int u = tid + it * 256;
            int r = u >> 5, c = (u & 31) * 8;
            const float* sp = sY + r * CY_STR + c;
            uint4 v;
            unsigned int* vp = (unsigned int*)&v;
            #pragma unroll
            for (int q = 0; q < 4; q++) {
                unsigned int lo = (unsigned int)__bfloat16_as_ushort(__float2bfloat16(sp[q * 2]));
                unsigned int hi = (unsigned int)__bfloat16_as_ushort(__float2bfloat16(sp[q * 2 + 1]));
                vp[q] = lo | (hi << 16);
            }
            *(uint4*)(out + (size_t)(row0 + r) * ldc + col0 + c) = v;
        }
    }
}

// ---------------- conv + silu (vectorized, bf16 in/out) ----------------
__global__ void conv_silu_k(const float* __restrict__ cw, const float* __restrict__ cb) {
    size_t idx = (size_t)blockIdx.x * 256 + threadIdx.x;       // one per 8 channels
    if (idx >= (size_t)R_TOT * DI / 8) return;
    int e0 = (int)((idx * 8) & (DI - 1));
    int r  = (int)(idx >> 9);
    int t  = r & (TSEQ - 1);

    float acc[8];
    const float4* cbp = (const float4*)(cb + e0);
    float4 cb0 = cbp[0], cb1 = cbp[1];
    acc[0] = cb0.x; acc[1] = cb0.y; acc[2] = cb0.z; acc[3] = cb0.w;
    acc[4] = cb1.x; acc[5] = cb1.y; acc[6] = cb1.z; acc[7] = cb1.w;

    #pragma unroll
    for (int k = 0; k < DCONV; k++) {
        int tt = t - 3 + k;
        if (tt >= 0) {
            uint4 pv = *(const uint4*)(g_proj + (size_t)(r - 3 + k) * WPAD + DI + e0);
            const float4* wp = (const float4*)(cw + k * DI + e0);
            float4 w0 = wp[0], w1 = wp[1];
            const unsigned int* pu = (const unsigned int*)&pv;
            float wv[8] = {w0.x, w0.y, w0.z, w0.w, w1.x, w1.y, w1.z, w1.w};
            #pragma unroll
            for (int q = 0; q < 4; q++) {
                float lo = __bfloat162float(__ushort_as_bfloat16((unsigned short)(pu[q] & 0xFFFF)));
                float hi = __bfloat162float(__ushort_as_bfloat16((unsigned short)(pu[q] >> 16)));
                acc[q * 2]     += lo * wv[q * 2];
                acc[q * 2 + 1] += hi * wv[q * 2 + 1];
            }
        }
    }
    uint4 ov;
    unsigned int* op = (unsigned int*)&ov;
    #pragma unroll
    for (int q = 0; q < 4; q++) {
        float a0 = acc[q * 2],     s0 = a0 / (1.f + expf(-a0));
        float a1 = acc[q * 2 + 1], s1 = a1 / (1.f + expf(-a1));
        unsigned int lo = (unsigned int)__bfloat16_as_ushort(__float2bfloat16(s0));
        unsigned int hi = (unsigned int)__bfloat16_as_ushort(__float2bfloat16(s1));
        op[q] = lo | (hi << 16);
    }
    *(uint4*)(g_act + idx * 8) = ov;
}

// ---------------- SSD pass1 (WMMA) ----------------
__global__ __launch_bounds__(256) void ssd_pass1_k(
    const float* __restrict__ A_log, const float* __restrict__ dt_bias)
{
    extern __shared__ char smraw[];
    __nv_bfloat16* sB  = (__nv_bfloat16*)smraw;
    __nv_bfloat16* sC  = sB + QQ * TS;
    __nv_bfloat16* sX  = sC + QQ * TS;
    __nv_bfloat16* sWB = sX + QQ * TS;
    __nv_bfloat16* sMb = sWB + QQ * TS;
    float* sMf  = (float*)(sMb + QQ * MS);
    float* sdt  = sMf + QQ * MS;
    float* scum = sdt + QQ;
    float* sw   = scum + QQ;

    int h = blockIdx.x, c = blockIdx.y, b = blockIdx.z;
    int tid = threadIdx.x;
    int wid = tid >> 5;
    int r0 = b * TSEQ + c * QQ;

    if (tid < QQ) {
        float d = __bfloat162float(g_proj[(size_t)(r0 + tid) * WPAD + 2 * DI + h]) + dt_bias[h];
        float dt = (d > 20.f) ? d : log1pf(expf(d));
        sdt[tid] = dt;
        scum[tid] = -expf(A_log[h]) * dt;
    }
    __syncthreads();
    for (int off = 1; off < QQ; off <<= 1) {
        float add = 0.f;
        if (tid < QQ && tid >= off) add = scum[tid - off];
        __syncthreads();
        if (tid < QQ) scum[tid] += add;
        __syncthreads();
    }
    if (tid < QQ) {
        g_cum[(size_t)(r0 + tid) * HH + h] = scum[tid];
        float clast = scum[QQ - 1];
        sw[tid] = expf(clast - scum[tid]) * sdt[tid];
        if (tid == 0) g_cdecay[(b * NC + c) * HH + h] = expf(clast);
    }
    __syncthreads();

    for (int idx = tid; idx < QQ * NS; idx += 256) {
        int row = idx >> 7, col = idx & 127;
        size_t pb = (size_t)(r0 + row) * WPAD;
        __nv_bfloat16 bv = g_proj[pb + 2 * DI + HH + col];
        sB[row * TS + col]  = bv;
        sC[row * TS + col]  = g_proj[pb + 2 * DI + HH + NS + col];
        sX[row * TS + col]  = g_act[(size_t)(r0 + row) * DI + h * PP + col];
        sWB[row * TS + col] = __float2bfloat16(__bfloat162float(bv) * sw[row]);
    }
    __syncthreads();

    // CB = C @ B^T
    {
        int wm = wid >> 1, wn = wid & 1;
        wmma::fragment<wmma::accumulator, 16, 16, 16, float> acc2[2];
        wmma::fill_fragment(acc2[0], 0.f);
        wmma::fill_fragment(acc2[1], 0.f);
        #pragma unroll
        for (int k = 0; k < 8; k++) {
            wmma::fragment<wmma::matrix_a, 16, 16, 16, __nv_bfloat16, wmma::row_major> a;
            wmma::load_matrix_sync(a, sC + (wm * 16) * TS + k * 16, TS);
            #pragma unroll
            for (int j2 = 0; j2 < 2; j2++) {
                wmma::fragment<wmma::matrix_b, 16, 16, 16, __nv_bfloat16, wmma::col_major> bfr;
                wmma::load_matrix_sync(bfr, sB + (wn * 32 + j2 * 16) * TS + k * 16, TS);
                wmma::mma_sync(acc2[j2], a, bfr, acc2[j2]);
            }
        }
        #pragma unroll
        for (int j2 = 0; j2 < 2; j2++)
            wmma::store_matrix_sync(sMf + (wm * 16) * MS + wn * 32 + j2 * 16, acc2[j2],
                                    MS, wmma::mem_row_major);
    }
    __syncthreads();

    for (int e = tid; e < QQ * QQ; e += 256) {
        int i = e >> 6, j = e & 63;
        float m = 0.f;
        if (j <= i)
            m = sMf[i * MS + j] * expf(scum[i] - scum[j]) * sdt[j];
        sMb[i * MS + j] = __float2bfloat16(m);
    }
    __syncthreads();

    // y_intra = M @ X
    {
        int wm = wid >> 1, wn = wid & 1;
        wmma::fragment<wmma::accumulator, 16, 16, 16, float> acc4[4];
        #pragma unroll
        for (int j = 0; j < 4; j++) wmma::fill_fragment(acc4[j], 0.f);
        #pragma unroll
        for (int k = 0; k < 4; k++) {
            wmma::fragment<wmma::matrix_a, 16, 16, 16, __nv_bfloat16, wmma::row_major> a;
            wmma::load_matrix_sync(a, sMb + (wm * 16) * MS + k * 16, MS);
            #pragma unroll
            for (int jj = 0; jj < 4; jj++) {
                wmma::fragment<wmma::matrix_b, 16, 16, 16, __nv_bfloat16, wmma::row_major> bfr;
                wmma::load_matrix_sync(bfr, sX + (k * 16) * TS + wn * 64 + jj * 16, TS);
                wmma::mma_sync(acc4[jj], a, bfr, acc4[jj]);
            }
        }
        #pragma unroll
        for (int jj = 0; jj < 4; jj++) {
            float* p = g_y + (size_t)(r0 + wm * 16) * DI + h * PP + wn * 64 + jj * 16;
            wmma::store_matrix_sync(p, acc4[jj], DI, wmma::mem_row_major);
        }
    }

    // state = WB^T @ X  (keep frags, stage fp32 -> smem, convert -> bf16 g_state)
    {
        int wm = wid >> 1, wn = wid & 1;
        size_t sbase = (size_t)((b * NC + c) * HH + h) * (NS * PP);
        wmma::fragment<wmma::accumulator, 16, 16, 16, float> accs[2][4];
        #pragma unroll
        for (int i2 = 0; i2 < 2; i2++)
            #pragma unroll
            for (int jj = 0; jj < 4; jj++) wmma::fill_fragment(accs[i2][jj], 0.f);
        #pragma unroll
        for (int k = 0; k < 4; k++) {
            wmma::fragment<wmma::matrix_a, 16, 16, 16, __nv_bfloat16, wmma::col_major> a[2];
            #pragma unroll
            for (int i2 = 0; i2 < 2; i2++)
                wmma::load_matrix_sync(a[i2], sWB + (k * 16) * TS + wm * 32 + i2 * 16, TS);
            #pragma unroll
            for (int jj = 0; jj < 4; jj++) {
                wmma::fragment<wmma::matrix_b, 16, 16, 16, __nv_bfloat16, wmma::row_major> bfr;
                wmma::load_matrix_sync(bfr, sX + (k * 16) * TS + wn * 64 + jj * 16, TS);
                #pragma unroll
                for (int i2 = 0; i2 < 2; i2++)
                    wmma::mma_sync(accs[i2][jj], a[i2], bfr, accs[i2][jj]);
            }
        }
        __syncthreads();   // all warps done reading sB/sC/sX/sWB
        float* sSt = (float*)smraw;   // 128*132 fp32 = 67584 B (fits in tile region)
        #pragma unroll
        for (int i2 = 0; i2 < 2; i2++)
            #pragma unroll
            for (int jj = 0; jj < 4; jj++)
                wmma::store_matrix_sync(sSt + (wm * 32 + i2 * 16) * ST_STR
                                            + wn * 64 + jj * 16,
                                        accs[i2][jj], ST_STR, wmma::mem_row_major);
        __syncthreads();
        #pragma unroll
        for (int it = 0; it < 8; it++) {
            int u = tid + it * 256;
            int r = u >> 4, c = (u & 15) * 8;
            const float* sp = sSt + r * ST_STR + c;
            uint4 v;
            unsigned int* vp = (unsigned int*)&v;
            #pragma unroll
            for (int q = 0; q < 4; q++) {
                unsigned int lo = (unsigned int)__bfloat16_as_ushort(__float2bfloat16(sp[q * 2]));
                unsigned int hi = (unsigned int)__bfloat16_as_ushort(__float2bfloat16(sp[q * 2 + 1]));
                vp[q] = lo | (hi << 16);
            }
            *(uint4*)(g_state + sbase + (size_t)r * PP + c) = v;
        }
    }
}

// ---------------- SSD pass2: inter-chunk scan (bf16 state, fp32 regs) ----------------
__global__ __launch_bounds__(512) void ssd_scan_k() {
    int h = blockIdx.x, b = blockIdx.y, sl = blockIdx.z;
    int tid = threadIdx.x;
    float st[8];
    #pragma unroll
    for (int k = 0; k < 8; k++) st[k] = 0.f;
    for (int c = 0; c < NC; c++) {
        size_t base = (size_t)((b * NC + c) * HH + h) * (NS * PP) + (size_t)sl * 4096;
        float dcy = g_cdecay[(b * NC + c) * HH + h];
        #pragma unroll
        for (int k = 0; k < 8; k++) {
            size_t idx = base + tid + k * 512;
            float loc = __bfloat162float(g_state[idx]);
            g_state[idx] = __float2bfloat16(st[k]);
            st[k] = fmaf(dcy, st[k], loc);
        }
    }
}

// ---------------- SSD pass3 (WMMA) ----------------
__global__ __launch_bounds__(256) void ssd_pass3_k(const float* __restrict__ Dv) {
    extern __shared__ char smraw[];
    __nv_bfloat16* sC = (__nv_bfloat16*)smraw;
    __nv_bfloat16* sS = sC + QQ * TS;
    float* sY   = (float*)(sS + NS * TS);
    float* scum = sY + QQ * YS;

    int h = blockIdx.x, c = blockIdx.y, b = blockIdx.z;
    int tid = threadIdx.x;
    int wid = tid >> 5;
    int r0 = b * TSEQ + c * QQ;
    size_t sbase = (size_t)((b * NC + c) * HH + h) * (NS * PP);

    for (int idx = tid; idx < NS * PP; idx += 256)
        sS[(idx >> 7) * TS + (idx & 127)] = g_state[sbase + idx];
    for (int idx = tid; idx < QQ * NS; idx += 256) {
        int row = idx >> 7, col = idx & 127;
        sC[row * TS + col] = g_proj[(size_t)(r0 + row) * WPAD + 2 * DI + HH + NS + col];
    }
    if (tid < QQ) scum[tid] = g_cum[(size_t)(r0 + tid) * HH + h];
    __syncthreads();

    {
        int wm = wid >> 1, wn = wid & 1;
        wmma::fragment<wmma::accumulator, 16, 16, 16, float> acc4[4];
        #pragma unroll
        for (int j = 0; j < 4; j++) wmma::fill_fragment(acc4[j], 0.f);
        #pragma unroll
        for (int k = 0; k < 8; k++) {
            wmma::fragment<wmma::matrix_a, 16, 16, 16, __nv_bfloat16, wmma::row_major> a;
            wmma::load_matrix_sync(a, sC + (wm * 16) * TS + k * 16, TS);
            #pragma unroll
            for (int jj = 0; jj < 4; jj++) {
                wmma::fragment<wmma::matrix_b, 16, 16, 16, __nv_bfloat16, wmma::row_major> bfr;
                wmma::load_matrix_sync(bfr, sS + (k * 16) * TS + wn * 64 + jj * 16, TS);
                wmma::mma_sync(acc4[jj], a, bfr, acc4[jj]);
            }
        }
        #pragma unroll
        for (int jj = 0; jj < 4; jj++)
            wmma::store_matrix_sync(sY + (wm * 16) * YS + wn * 64 + jj * 16, acc4[jj],
                                    YS, wmma::mem_row_major);
    }
    __syncthreads();

    for (int o = tid; o < QQ * PP; o += 256) {
        int i = o >> 7, p = o & 127;
        float yi = expf(scum[i]) * sY[i * YS + p];
        int d = h * PP + p;
        size_t r = (size_t)(r0 + i);
        float act = __bfloat162float(g_act[r * DI + d]);
        float val = g_y[r * DI + d] + yi + Dv[d] * act;
        float gate = __bfloat162float(g_proj[r * WPAD + d]);
        float sg = gate / (1.f + expf(-gate));
        g_yb[r * DI + d] = __float2bfloat16(val * sg);
    }
}

// ---------------- launch ----------------
extern "C" void kernel_launch(void* const* d_in, const int* in_sizes, int n_in,
                              void* d_out, int out_size) {
    const float* x         = (const float*)d_in[0];
    const float* normscale = (const float*)d_in[1];
    const float* w1        = (const float*)d_in[2];
    const float* convw     = (const float*)d_in[3];
    const float* convb     = (const float*)d_in[4];
    const float* A_log     = (const float*)d_in[5];
    const float* dt_bias   = (const float*)d_in[6];
    const float* Dv        = (const float*)d_in[7];
    const float* w2        = (const float*)d_in[8];
    float* out             = (float*)d_out;

    void *p_h, *p_w1, *p_w2, *p_proj, *p_yb;
    cudaGetSymbolAddress(&p_h, g_h);
    cudaGetSymbolAddress(&p_w1, g_w1);
    cudaGetSymbolAddress(&p_w2, g_w2);
    cudaGetSymbolAddress(&p_proj, g_proj);
    cudaGetSymbolAddress(&p_yb, g_yb);

    const int smemG = 128 * CY_STR * 4;                          // 135168 (covers stages too)
    const int smem1 = (4 * QQ * TS + QQ * MS) * 2 + (QQ * MS + 3 * QQ) * 4;
    const int smem3 = (QQ * TS + NS * TS) * 2 + (QQ * YS + QQ) * 4;
    cudaFuncSetAttribute(gemm_bf16<0>, cudaFuncAttributeMaxDynamicSharedMemorySize, smemG);
    cudaFuncSetAttribute(gemm_bf16<1>, cudaFuncAttributeMaxDynamicSharedMemorySize, smemG);
    cudaFuncSetAttribute(ssd_pass1_k, cudaFuncAttributeMaxDynamicSharedMemorySize, smem1);
    cudaFuncSetAttribute(ssd_pass3_k, cudaFuncAttributeMaxDynamicSharedMemorySize, smem3);

    {
        size_t n1 = (size_t)E * WPAD;
        conv_w1_k<<<(unsigned)((n1 + 255) / 256), 256>>>(w1);
        size_t n2 = (size_t)DI * E;
        conv_w2_k<<<(unsigned)((n2 + 255) / 256), 256>>>(w2);
    }
    rmsnorm_k<<<R_TOT, 256>>>(x, normscale);
    {
        dim3 grid(WPAD / 256, R_TOT / 128);
        gemm_bf16<0><<<grid, 256, smemG>>>((const __nv_bfloat16*)p_h,
                                           (const __nv_bfloat16*)p_w1,
                                           p_proj, nullptr, E, E, WPAD, WPAD);
    }
    {
        size_t n = (size_t)R_TOT * DI / 8;
        conv_silu_k<<<(unsigned)((n + 255) / 256), 256>>>(convw, convb);
    }
    {
        dim3 grid(HH, NC, BATCH);
        ssd_pass1_k<<<grid, 256, smem1>>>(A_log, dt_bias);
    }
    {
        dim3 grid(HH, BATCH, 4);
        ssd_scan_k<<<grid, 512>>>();
    }
    {
        dim3 grid(HH, NC, BATCH);
        ssd_pass3_k<<<grid, 256, smem3>>>(Dv);
    }
    {
        dim3 grid(E / 256, R_TOT / 128);
        gemm_bf16<1><<<grid, 256, smemG>>>((const __nv_bfloat16*)p_yb,
                                           (const __nv_bfloat16*)p_w2,
                                           out, x, DI, DI, E, E);
    }
}

// round 15
// speedup vs baseline: 2.2041x; 1.0517x over previous
#include <cstdint>
#include <cuda_runtime.h>
#include <cuda_bf16.h>
#include <mma.h>
#include <math.h>

using namespace nvcuda;

// ---------------- problem constants ----------------
#define BATCH   2
#define TSEQ    2048
#define R_TOT   4096
#define E       2048
#define DI      4096
#define HH      32
#define PP      128
#define NS      128
#define QQ      64
#define NC      32
#define PROJW   8480
#define WPAD    8576          // padded to multiple of 128
#define DCONV   4

#define TS      136      // bf16 tile stride
#define MS      72       // M tile stride
#define YS      132      // fp32 y tile stride

// GEMM tiling: CTA 128x128, warp 64x32, BK=64, 3 stages
#define GBK     64
#define SA_STR  72       // A smem stride (64 + 8)
#define SB_STR  136      // B smem stride (128 + 8)
#define CY_STR  132      // fp32 staging stride (epilogue)
#define STAGE_EL (128 * SA_STR + GBK * SB_STR)   // 17920 elems = 35840 B

// ---------------- scratch ----------------
__device__ __nv_bfloat16 g_h[(size_t)R_TOT * E];
__device__ __nv_bfloat16 g_w1[(size_t)E * WPAD];
__device__ __nv_bfloat16 g_w2[(size_t)DI * E];
__device__ __nv_bfloat16 g_proj[(size_t)R_TOT * WPAD];
__device__ __nv_bfloat16 g_act[(size_t)R_TOT * DI];
__device__ __nv_bfloat16 g_y[(size_t)R_TOT * DI];
__device__ __nv_bfloat16 g_yb[(size_t)R_TOT * DI];
__device__ __nv_bfloat16 g_state[(size_t)BATCH * NC * HH * NS * PP];
__device__ float         g_cdecay[BATCH * NC * HH];
__device__ float         g_cum[(size_t)R_TOT * HH];

// ---------------- cp.async helpers ----------------
__device__ __forceinline__ void cpa16(void* dst, const void* src) {
    unsigned int d = (unsigned int)__cvta_generic_to_shared(dst);
    asm volatile("cp.async.cg.shared.global [%0], [%1], 16;\n" :: "r"(d), "l"(src));
}
#define CP_COMMIT() asm volatile("cp.async.commit_group;\n" ::: "memory")
#define CP_WAIT0()  asm volatile("cp.async.wait_group 0;\n" ::: "memory")
#define CP_WAIT1()  asm volatile("cp.async.wait_group 1;\n" ::: "memory")

// ---------------- weight conversion (fp32 -> bf16) ----------------
__global__ void conv_w1_k(const float* __restrict__ w) {
    size_t idx = (size_t)blockIdx.x * 256 + threadIdx.x;
    if (idx >= (size_t)E * WPAD) return;
    int row = (int)(idx / WPAD);
    int col = (int)(idx % WPAD);
    float v = (col < PROJW) ? w[(size_t)row * PROJW + col] : 0.f;
    g_w1[idx] = __float2bfloat16(v);
}
__global__ void conv_w2_k(const float* __restrict__ w) {
    size_t idx = (size_t)blockIdx.x * 256 + threadIdx.x;
    if (idx >= (size_t)DI * E) return;
    g_w2[idx] = __float2bfloat16(w[idx]);
}

// ---------------- rmsnorm ----------------
__global__ void rmsnorm_k(const float* __restrict__ x, const float* __restrict__ scale) {
    int r = blockIdx.x;
    int tid = threadIdx.x;
    const float* xr = x + (size_t)r * E;
    __shared__ float red[256];
    float ss = 0.f;
    for (int i = tid; i < E; i += 256) { float v = xr[i]; ss += v * v; }
    red[tid] = ss; __syncthreads();
    for (int s = 128; s > 0; s >>= 1) {
        if (tid < s) red[tid] += red[tid + s];
        __syncthreads();
    }
    float rstd = rsqrtf(red[0] / (float)E + 1e-6f);
    for (int i = tid; i < E; i += 256)
        g_h[(size_t)r * E + i] = __float2bfloat16(xr[i] * rstd * scale[i]);
}

// ---------------- bf16 WMMA GEMM, CTA 128x128, warp 64x32, BK=64, 3 stages ----------------
// C = A @ B (+ res). MODE 0: store bf16 (staged). MODE 1: store fp32 + residual.
template<int MODE>
__global__ __launch_bounds__(256, 2) void gemm_bf16(
    const __nv_bfloat16* __restrict__ A, const __nv_bfloat16* __restrict__ Bw,
    void* __restrict__ Cout, const float* __restrict__ res,
    int K, int lda, int ldb, int ldc)
{
    extern __shared__ char smraw[];
    __nv_bfloat16* sbase = (__nv_bfloat16*)smraw;

    int tid = threadIdx.x;
    int wid = tid >> 5;
    int warp_m = wid >> 2;
    int warp_n = wid & 3;
    int row0 = blockIdx.y * 128;
    int col0 = blockIdx.x * 128;

    wmma::fragment<wmma::accumulator, 16, 16, 16, float> acc[4][2];
    if (MODE == 1) {
        #pragma unroll
        for (int i = 0; i < 4; i++)
            #pragma unroll
            for (int j = 0; j < 2; j++) {
                const float* p = res + (size_t)(row0 + warp_m * 64 + i * 16) * ldc
                                     + col0 + warp_n * 32 + j * 16;
                wmma::load_matrix_sync(acc[i][j], p, ldc, wmma::mem_row_major);
            }
    } else {
        #pragma unroll
        for (int i = 0; i < 4; i++)
            #pragma unroll
            for (int j = 0; j < 2; j++)
                wmma::fill_fragment(acc[i][j], 0.f);
    }

    int nst = K / GBK;

    // stage loader
    auto load_stage = [&](int stage, int k0) {
        __nv_bfloat16* sA = sbase + stage * STAGE_EL;
        __nv_bfloat16* sB = sA + 128 * SA_STR;
        #pragma unroll
        for (int it = 0; it < 4; it++) {
            int u = tid + it * 256;
            int r = u >> 3, c = (u & 7) * 8;
            cpa16(sA + r * SA_STR + c, A + (size_t)(row0 + r) * lda + k0 + c);
        }
        #pragma unroll
        for (int it = 0; it < 4; it++) {
            int u = tid + it * 256;
            int r = u >> 4, c = (u & 15) * 8;
            cpa16(sB + r * SB_STR + c, Bw + (size_t)(k0 + r) * ldb + col0 + c);
        }
        CP_COMMIT();
    };

    load_stage(0, 0);
    if (nst > 1) load_stage(1, GBK);

    for (int s2 = 0; s2 < nst; s2++) {
        if (s2 >= nst - 1) { CP_WAIT0(); } else { CP_WAIT1(); }
        __syncthreads();
        if (s2 + 2 < nst) load_stage((s2 + 2) % 3, (s2 + 2) * GBK);

        __nv_bfloat16* sA = sbase + (s2 % 3) * STAGE_EL;
        __nv_bfloat16* sB = sA + 128 * SA_STR;
        #pragma unroll
        for (int kk = 0; kk < GBK; kk += 16) {
            wmma::fragment<wmma::matrix_a, 16, 16, 16, __nv_bfloat16, wmma::row_major> af[4];
            wmma::fragment<wmma::matrix_b, 16, 16, 16, __nv_bfloat16, wmma::row_major> bf[2];
            #pragma unroll
            for (int i = 0; i < 4; i++)
                wmma::load_matrix_sync(af[i], sA + (warp_m * 64 + i * 16) * SA_STR + kk, SA_STR);
            #pragma unroll
            for (int j = 0; j < 2; j++)
                wmma::load_matrix_sync(bf[j], sB + kk * SB_STR + warp_n * 32 + j * 16, SB_STR);
            #pragma unroll
            for (int i = 0; i < 4; i++)
                #pragma unroll
                for (int j = 0; j < 2; j++)
                    wmma::mma_sync(acc[i][j], af[i], bf[j], acc[i][j]);
        }
    }
    __syncthreads();

    if (MODE == 1) {
        float* out = (float*)Cout;
        #pragma unroll
        for (int i = 0; i < 4; i++)
            #pragma unroll
            for (int j = 0; j < 2; j++) {
                float* p = out + (size_t)(row0 + warp_m * 64 + i * 16) * ldc
                               + col0 + warp_n * 32 + j * 16;
                wmma::store_matrix_sync(p, acc[i][j], ldc, wmma::mem_row_major);
            }
    } else {
        float* sY = (float*)smraw;   // 128*132*4 = 67584 <= 107520
        #pragma unroll
        for (int i = 0; i < 4; i++)
            #pragma unroll
            for (int j = 0; j < 2; j++)
                wmma::store_matrix_sync(sY + (warp_m * 64 + i * 16) * CY_STR
                                           + warp_n * 32 + j * 16,
                                        acc[i][j], CY_STR, wmma::mem_row_major);
        __syncthreads();
        __nv_bfloat16* out = (__nv_bfloat16*)Cout;
        #pragma unroll
        for (int it = 0; it < 8; it++) {
            int u = tid + it * 256;
            int r = u >> 4, c = (u & 15) * 8;
            const float* sp = sY + r * CY_STR + c;
            uint4 v;
            unsigned int* vp = (unsigned int*)&v;
            #pragma unroll
            for (int q = 0; q < 4; q++) {
                unsigned int lo = (unsigned int)__bfloat16_as_ushort(__float2bfloat16(sp[q * 2]));
                unsigned int hi = (unsigned int)__bfloat16_as_ushort(__float2bfloat16(sp[q * 2 + 1]));
                vp[q] = lo | (hi << 16);
            }
            *(uint4*)(out + (size_t)(row0 + r) * ldc + col0 + c) = v;
        }
    }
}

// ---------------- SSD pass1 (WMMA) with fused conv+silu ----------------
__global__ __launch_bounds__(256) void ssd_pass1_k(
    const float* __restrict__ A_log, const float* __restrict__ dt_bias,
    const float* __restrict__ cw, const float* __restrict__ cb)
{
    extern __shared__ char smraw[];
    __nv_bfloat16* sB  = (__nv_bfloat16*)smraw;
    __nv_bfloat16* sC  = sB + QQ * TS;
    __nv_bfloat16* sX  = sC + QQ * TS;
    __nv_bfloat16* sWB = sX + QQ * TS;
    __nv_bfloat16* sMb = sWB + QQ * TS;
    float* sMf  = (float*)(sMb + QQ * MS);
    float* sdt  = sMf + QQ * MS;
    float* scum = sdt + QQ;
    float* sw   = scum + QQ;

    int h = blockIdx.x, c = blockIdx.y, b = blockIdx.z;
    int tid = threadIdx.x;
    int wid = tid >> 5;
    int r0 = b * TSEQ + c * QQ;

    if (tid < QQ) {
        float d = __bfloat162float(g_proj[(size_t)(r0 + tid) * WPAD + 2 * DI + h]) + dt_bias[h];
        float dt = (d > 20.f) ? d : log1pf(expf(d));
        sdt[tid] = dt;
        scum[tid] = -expf(A_log[h]) * dt;
    }
    __syncthreads();
    for (int off = 1; off < QQ; off <<= 1) {
        float add = 0.f;
        if (tid < QQ && tid >= off) add = scum[tid - off];
        __syncthreads();
        if (tid < QQ) scum[tid] += add;
        __syncthreads();
    }
    if (tid < QQ) {
        g_cum[(size_t)(r0 + tid) * HH + h] = scum[tid];
        float clast = scum[QQ - 1];
        sw[tid] = expf(clast - scum[tid]) * sdt[tid];
        if (tid == 0) g_cdecay[(b * NC + c) * HH + h] = expf(clast);
    }
    __syncthreads();

    // ---- B, C tiles + weighted B ----
    for (int idx = tid; idx < QQ * NS; idx += 256) {
        int row = idx >> 7, col = idx & 127;
        size_t pb = (size_t)(r0 + row) * WPAD;
        __nv_bfloat16 bv = g_proj[pb + 2 * DI + HH + col];
        sB[row * TS + col]  = bv;
        sC[row * TS + col]  = g_proj[pb + 2 * DI + HH + NS + col];
        sWB[row * TS + col] = __float2bfloat16(__bfloat162float(bv) * sw[row]);
    }

    // ---- X tile via fused causal conv + silu (8-wide vectors) ----
    for (int v = tid; v < QQ * NS / 8; v += 256) {
        int row = v >> 4;
        int c8  = (v & 15) * 8;
        int gr  = r0 + row;
        int t   = gr & (TSEQ - 1);
        int d0  = h * PP + c8;

        float acc[8];
        const float4* cbp = (const float4*)(cb + d0);
        float4 cb0 = cbp[0], cb1 = cbp[1];
        acc[0] = cb0.x; acc[1] = cb0.y; acc[2] = cb0.z; acc[3] = cb0.w;
        acc[4] = cb1.x; acc[5] = cb1.y; acc[6] = cb1.z; acc[7] = cb1.w;

        #pragma unroll
        for (int k = 0; k < DCONV; k++) {
            int tt = t - 3 + k;
            if (tt >= 0) {
                uint4 pv = *(const uint4*)(g_proj + (size_t)(gr - 3 + k) * WPAD + DI + d0);
                const float4* wp = (const float4*)(cw + k * DI + d0);
                float4 w0 = wp[0], w1 = wp[1];
                const unsigned int* pu = (const unsigned int*)&pv;
                float wv[8] = {w0.x, w0.y, w0.z, w0.w, w1.x, w1.y, w1.z, w1.w};
                #pragma unroll
                for (int q = 0; q < 4; q++) {
                    float lo = __bfloat162float(__ushort_as_bfloat16((unsigned short)(pu[q] & 0xFFFF)));
                    float hi = __bfloat162float(__ushort_as_bfloat16((unsigned short)(pu[q] >> 16)));
                    acc[q * 2]     += lo * wv[q * 2];
                    acc[q * 2 + 1] += hi * wv[q * 2 + 1];
                }
            }
        }
        uint4 ov;
        unsigned int* op = (unsigned int*)&ov;
        #pragma unroll
        for (int q = 0; q < 4; q++) {
            float a0 = acc[q * 2],     s0 = a0 / (1.f + expf(-a0));
            float a1 = acc[q * 2 + 1], s1 = a1 / (1.f + expf(-a1));
            unsigned int lo = (unsigned int)__bfloat16_as_ushort(__float2bfloat16(s0));
            unsigned int hi = (unsigned int)__bfloat16_as_ushort(__float2bfloat16(s1));
            op[q] = lo | (hi << 16);
        }
        *(uint4*)(sX + row * TS + c8) = ov;
        *(uint4*)(g_act + (size_t)gr * DI + d0) = ov;
    }
    __syncthreads();

    // ---- CB = C @ B^T ----
    {
        int wm = wid >> 1, wn = wid & 1;
        wmma::fragment<wmma::accumulator, 16, 16, 16, float> acc2[2];
        wmma::fill_fragment(acc2[0], 0.f);
        wmma::fill_fragment(acc2[1], 0.f);
        #pragma unroll
        for (int k = 0; k < 8; k++) {
            wmma::fragment<wmma::matrix_a, 16, 16, 16, __nv_bfloat16, wmma::row_major> a;
            wmma::load_matrix_sync(a, sC + (wm * 16) * TS + k * 16, TS);
            #pragma unroll
            for (int j2 = 0; j2 < 2; j2++) {
                wmma::fragment<wmma::matrix_b, 16, 16, 16, __nv_bfloat16, wmma::col_major> bfr;
                wmma::load_matrix_sync(bfr, sB + (wn * 32 + j2 * 16) * TS + k * 16, TS);
                wmma::mma_sync(acc2[j2], a, bfr, acc2[j2]);
            }
        }
        #pragma unroll
        for (int j2 = 0; j2 < 2; j2++)
            wmma::store_matrix_sync(sMf + (wm * 16) * MS + wn * 32 + j2 * 16, acc2[j2],
                                    MS, wmma::mem_row_major);
    }
    __syncthreads();

    for (int e = tid; e < QQ * QQ; e += 256) {
        int i = e >> 6, j = e & 63;
        float m = 0.f;
        if (j <= i)
            m = sMf[i * MS + j] * expf(scum[i] - scum[j]) * sdt[j];
        sMb[i * MS + j] = __float2bfloat16(m);
    }
    __syncthreads();

    // ---- y_intra = M @ X -> stage fp32 in (sB..sC) region -> bf16 g_y ----
    {
        int wm = wid >> 1, wn = wid & 1;
        wmma::fragment<wmma::accumulator, 16, 16, 16, float> acc4[4];
        #pragma unroll
        for (int j = 0; j < 4; j++) wmma::fill_fragment(acc4[j], 0.f);
        #pragma unroll
        for (int k = 0; k < 4; k++) {
            wmma::fragment<wmma::matrix_a, 16, 16, 16, __nv_bfloat16, wmma::row_major> a;
            wmma::load_matrix_sync(a, sMb + (wm * 16) * MS + k * 16, MS);
            #pragma unroll
            for (int jj = 0; jj < 4; jj++) {
                wmma::fragment<wmma::matrix_b, 16, 16, 16, __nv_bfloat16, wmma::row_major> bfr;
                wmma::load_matrix_sync(bfr, sX + (k * 16) * TS + wn * 64 + jj * 16, TS);
                wmma::mma_sync(acc4[jj], a, bfr, acc4[jj]);
            }
        }
        float* sYst = (float*)smraw;   // 64*132*4 = 33792 <= sB+sC region (34816)
        #pragma unroll
        for (int jj = 0; jj < 4; jj++)
            wmma::store_matrix_sync(sYst + (wm * 16) * YS + wn * 64 + jj * 16,
                                    acc4[jj], YS, wmma::mem_row_major);
        __syncthreads();
        #pragma unroll
        for (int it = 0; it < 4; it++) {
            int u = tid + it * 256;
            int r = u >> 4, cc = (u & 15) * 8;
            const float* sp = sYst + r * YS + cc;
            uint4 vv;
            unsigned int* vp = (unsigned int*)&vv;
            #pragma unroll
            for (int q = 0; q < 4; q++) {
                unsigned int lo = (unsigned int)__bfloat16_as_ushort(__float2bfloat16(sp[q * 2]));
                unsigned int hi = (unsigned int)__bfloat16_as_ushort(__float2bfloat16(sp[q * 2 + 1]));
                vp[q] = lo | (hi << 16);
            }
            *(uint4*)(g_y + (size_t)(r0 + r) * DI + h * PP + cc) = vv;
        }
    }

    // ---- state = WB^T @ X -> stage fp32 -> bf16 g_state ----
    {
        int wm = wid >> 1, wn = wid & 1;
        size_t sbase = (size_t)((b * NC + c) * HH + h) * (NS * PP);
        wmma::fragment<wmma::accumulator, 16, 16, 16, float> accs[2][4];
        #pragma unroll
        for (int i2 = 0; i2 < 2; i2++)
            #pragma unroll
            for (int jj = 0; jj < 4; jj++) wmma::fill_fragment(accs[i2][jj], 0.f);
        #pragma unroll
        for (int k = 0; k < 4; k++) {
            wmma::fragment<wmma::matrix_a, 16, 16, 16, __nv_bfloat16, wmma::col_major> a[2];
            #pragma unroll
            for (int i2 = 0; i2 < 2; i2++)
                wmma::load_matrix_sync(a[i2], sWB + (k * 16) * TS + wm * 32 + i2 * 16, TS);
            #pragma unroll
            for (int jj = 0; jj < 4; jj++) {
                wmma::fragment<wmma::matrix_b, 16, 16, 16, __nv_bfloat16, wmma::row_major> bfr;
                wmma::load_matrix_sync(bfr, sX + (k * 16) * TS + wn * 64 + jj * 16, TS);
                #pragma unroll
                for (int i2 = 0; i2 < 2; i2++)
                    wmma::mma_sync(accs[i2][jj], a[i2], bfr, accs[i2][jj]);
            }
        }
        __syncthreads();   // y-convert reads done; sX/sWB reads done
        float* sSt = (float*)smraw;   // 128*132*4 = 67584 spans sB..sWB (69632)
        #pragma unroll
        for (int i2 = 0; i2 < 2; i2++)
            #pragma unroll
            for (int jj = 0; jj < 4; jj++)
                wmma::store_matrix_sync(sSt + (wm * 32 + i2 * 16) * YS
                                            + wn * 64 + jj * 16,
                                        accs[i2][jj], YS, wmma::mem_row_major);
        __syncthreads();
        #pragma unroll
        for (int it = 0; it < 8; it++) {
            int u = tid + it * 256;
            int r = u >> 4, cc = (u & 15) * 8;
            const float* sp = sSt + r * YS + cc;
            uint4 vv;
            unsigned int* vp = (unsigned int*)&vv;
            #pragma unroll
            for (int q = 0; q < 4; q++) {
                unsigned int lo = (unsigned int)__bfloat16_as_ushort(__float2bfloat16(sp[q * 2]));
                unsigned int hi = (unsigned int)__bfloat16_as_ushort(__float2bfloat16(sp[q * 2 + 1]));
                vp[q] = lo | (hi << 16);
            }
            *(uint4*)(g_state + sbase + (size_t)r * PP + cc) = vv;
        }
    }
}

// ---------------- SSD pass2: inter-chunk scan (bf16 state, fp32 regs) ----------------
__global__ __launch_bounds__(512) void ssd_scan_k() {
    int h = blockIdx.x, b = blockIdx.y, sl = blockIdx.z;
    int tid = threadIdx.x;
    float st[8];
    #pragma unroll
    for (int k = 0; k < 8; k++) st[k] = 0.f;
    for (int c = 0; c < NC; c++) {
        size_t base = (size_t)((b * NC + c) * HH + h) * (NS * PP) + (size_t)sl * 4096;
        float dcy = g_cdecay[(b * NC + c) * HH + h];
        #pragma unroll
        for (int k = 0; k < 8; k++) {
            size_t idx = base + tid + k * 512;
            float loc = __bfloat162float(g_state[idx]);
            g_state[idx] = __float2bfloat16(st[k]);
            st[k] = fmaf(dcy, st[k], loc);
        }
    }
}

// ---------------- SSD pass3 (WMMA) ----------------
__global__ __launch_bounds__(256) void ssd_pass3_k(const float* __restrict__ Dv) {
    extern __shared__ char smraw[];
    __nv_bfloat16* sC = (__nv_bfloat16*)smraw;
    __nv_bfloat16* sS = sC + QQ * TS;
    float* sY   = (float*)(sS + NS * TS);
    float* scum = sY + QQ * YS;

    int h = blockIdx.x, c = blockIdx.y, b = blockIdx.z;
    int tid = threadIdx.x;
    int wid = tid >> 5;
    int r0 = b * TSEQ + c * QQ;
    size_t sbase = (size_t)((b * NC + c) * HH + h) * (NS * PP);

    for (int idx = tid; idx < NS * PP; idx += 256)
        sS[(idx >> 7) * TS + (idx & 127)] = g_state[sbase + idx];
    for (int idx = tid; idx < QQ * NS; idx += 256) {
        int row = idx >> 7, col = idx & 127;
        sC[row * TS + col] = g_proj[(size_t)(r0 + row) * WPAD + 2 * DI + HH + NS + col];
    }
    if (tid < QQ) scum[tid] = g_cum[(size_t)(r0 + tid) * HH + h];
    __syncthreads();

    {
        int wm = wid >> 1, wn = wid & 1;
        wmma::fragment<wmma::accumulator, 16, 16, 16, float> acc4[4];
        #pragma unroll
        for (int j = 0; j < 4; j++) wmma::fill_fragment(acc4[j], 0.f);
        #pragma unroll
        for (int k = 0; k < 8; k++) {
            wmma::fragment<wmma::matrix_a, 16, 16, 16, __nv_bfloat16, wmma::row_major> a;
            wmma::load_matrix_sync(a, sC + (wm * 16) * TS + k * 16, TS);
            #pragma unroll
            for (int jj = 0; jj < 4; jj++) {
                wmma::fragment<wmma::matrix_b, 16, 16, 16, __nv_bfloat16, wmma::row_major> bfr;
                wmma::load_matrix_sync(bfr, sS + (k * 16) * TS + wn * 64 + jj * 16, TS);
                wmma::mma_sync(acc4[jj], a, bfr, acc4[jj]);
            }
        }
        #pragma unroll
        for (int jj = 0; jj < 4; jj++)
            wmma::store_matrix_sync(sY + (wm * 16) * YS + wn * 64 + jj * 16, acc4[jj],
                                    YS, wmma::mem_row_major);
    }
    __syncthreads();

    for (int o = tid; o < QQ * PP; o += 256) {
        int i = o >> 7, p = o & 127;
        float yi = expf(scum[i]) * sY[i * YS + p];
        int d = h * PP + p;
        size_t r = (size_t)(r0 + i);
        float act = __bfloat162float(g_act[r * DI + d]);
        float val = __bfloat162float(g_y[r * DI + d]) + yi + Dv[d] * act;
        float gate = __bfloat162float(g_proj[r * WPAD + d]);
        float sg = gate / (1.f + expf(-gate));
        g_yb[r * DI + d] = __float2bfloat16(val * sg);
    }
}

// ---------------- launch ----------------
extern "C" void kernel_launch(void* const* d_in, const int* in_sizes, int n_in,
                              void* d_out, int out_size) {
    const float* x         = (const float*)d_in[0];
    const float* normscale = (const float*)d_in[1];
    const float* w1        = (const float*)d_in[2];
    const float* convw     = (const float*)d_in[3];
    const float* convb     = (const float*)d_in[4];
    const float* A_log     = (const float*)d_in[5];
    const float* dt_bias   = (const float*)d_in[6];
    const float* Dv        = (const float*)d_in[7];
    const float* w2        = (const float*)d_in[8];
    float* out             = (float*)d_out;

    void *p_h, *p_w1, *p_w2, *p_proj, *p_yb;
    cudaGetSymbolAddress(&p_h, g_h);
    cudaGetSymbolAddress(&p_w1, g_w1);
    cudaGetSymbolAddress(&p_w2, g_w2);
    cudaGetSymbolAddress(&p_proj, g_proj);
    cudaGetSymbolAddress(&p_yb, g_yb);

    const int smemG = 3 * STAGE_EL * 2;                          // 107520
    const int smem1 = (4 * QQ * TS + QQ * MS) * 2 + (QQ * MS + 3 * QQ) * 4;
    const int smem3 = (QQ * TS + NS * TS) * 2 + (QQ * YS + QQ) * 4;
    cudaFuncSetAttribute(gemm_bf16<0>, cudaFuncAttributeMaxDynamicSharedMemorySize, smemG);
    cudaFuncSetAttribute(gemm_bf16<1>, cudaFuncAttributeMaxDynamicSharedMemorySize, smemG);
    cudaFuncSetAttribute(ssd_pass1_k, cudaFuncAttributeMaxDynamicSharedMemorySize, smem1);
    cudaFuncSetAttribute(ssd_pass3_k, cudaFuncAttributeMaxDynamicSharedMemorySize, smem3);

    {
        size_t n1 = (size_t)E * WPAD;
        conv_w1_k<<<(unsigned)((n1 + 255) / 256), 256>>>(w1);
        size_t n2 = (size_t)DI * E;
        conv_w2_k<<<(unsigned)((n2 + 255) / 256), 256>>>(w2);
    }
    rmsnorm_k<<<R_TOT, 256>>>(x, normscale);
    {
        dim3 grid(WPAD / 128, R_TOT / 128);
        gemm_bf16<0><<<grid, 256, smemG>>>((const __nv_bfloat16*)p_h,
                                           (const __nv_bfloat16*)p_w1,
                                           p_proj, nullptr, E, E, WPAD, WPAD);
    }
    {
        dim3 grid(HH, NC, BATCH);
        ssd_pass1_k<<<grid, 256, smem1>>>(A_log, dt_bias, convw, convb);
    }
    {
        dim3 grid(HH, BATCH, 4);
        ssd_scan_k<<<grid, 512>>>();
    }
    {
        dim3 grid(HH, NC, BATCH);
        ssd_pass3_k<<<grid, 256, smem3>>>(Dv);
    }
    {
        dim3 grid(E / 128, R_TOT / 128);
        gemm_bf16<1><<<grid, 256, smemG>>>((const __nv_bfloat16*)p_yb,
                                           (const __nv_bfloat16*)p_w2,
                                           out, x, DI, DI, E, E);
    }
}

// round 17
// speedup vs baseline: 2.9608x; 1.3433x over previous
#include <cstdint>
#include <cuda_runtime.h>
#include <cuda_bf16.h>
#include <mma.h>
#include <math.h>

using namespace nvcuda;

// ---------------- problem constants ----------------
#define BATCH   2
#define TSEQ    2048
#define R_TOT   4096
#define E       2048
#define DI      4096
#define HH      32
#define PP      128
#define NS      128
#define QQ      64
#define NC      32
#define PROJW   8480
#define WPAD    8576          // padded to multiple of 128
#define DCONV   4

#define TS      136      // bf16 tile stride
#define MS      72       // M tile stride
#define YS      132      // fp32 y tile stride

// GEMM tiling: CTA 128x128, warp 64x32, BK=64, 3 stages
#define GBK     64
#define SA_STR  72
#define SB_STR  136
#define CY_STR  132
#define STAGE_EL (128 * SA_STR + GBK * SB_STR)   // 17920 elems = 35840 B

// ---------------- scratch ----------------
__device__ __nv_bfloat16 g_h[(size_t)R_TOT * E];
__device__ __nv_bfloat16 g_w1[(size_t)E * WPAD];
__device__ __nv_bfloat16 g_w2[(size_t)DI * E];
__device__ __nv_bfloat16 g_proj[(size_t)R_TOT * WPAD];
__device__ __nv_bfloat16 g_act[(size_t)R_TOT * DI];
__device__ __nv_bfloat16 g_y[(size_t)R_TOT * DI];
__device__ __nv_bfloat16 g_yb[(size_t)R_TOT * DI];
__device__ __nv_bfloat16 g_state[(size_t)BATCH * NC * HH * NS * PP];
__device__ float         g_cdecay[BATCH * NC * HH];
__device__ float         g_cum[(size_t)R_TOT * HH];

// ---------------- helpers ----------------
__device__ __forceinline__ void cpa16(void* dst, const void* src) {
    unsigned int d = (unsigned int)__cvta_generic_to_shared(dst);
    asm volatile("cp.async.cg.shared.global [%0], [%1], 16;\n" :: "r"(d), "l"(src));
}
#define CP_COMMIT() asm volatile("cp.async.commit_group;\n" ::: "memory")
#define CP_WAIT0()  asm volatile("cp.async.wait_group 0;\n" ::: "memory")
#define CP_WAIT1()  asm volatile("cp.async.wait_group 1;\n" ::: "memory")

__device__ __forceinline__ float bf_lo(unsigned int u) {
    return __bfloat162float(__ushort_as_bfloat16((unsigned short)(u & 0xFFFF)));
}
__device__ __forceinline__ float bf_hi(unsigned int u) {
    return __bfloat162float(__ushort_as_bfloat16((unsigned short)(u >> 16)));
}
__device__ __forceinline__ unsigned int bf_pack(float a, float b) {
    unsigned int lo = (unsigned int)__bfloat16_as_ushort(__float2bfloat16(a));
    unsigned int hi = (unsigned int)__bfloat16_as_ushort(__float2bfloat16(b));
    return lo | (hi << 16);
}

// ---------------- weight conversion (vectorized) ----------------
__global__ void conv_w1_k(const float* __restrict__ w) {
    size_t idx = (size_t)blockIdx.x * 256 + threadIdx.x;   // one per 4 elems
    if (idx >= (size_t)E * WPAD / 4) return;
    size_t e0 = idx * 4;
    int row = (int)(e0 / WPAD);
    int col = (int)(e0 % WPAD);
    uint2 ov;
    if (col < PROJW) {     // groups fully valid or fully pad (both mult of 4)
        float4 v = *(const float4*)(w + (size_t)row * PROJW + col);
        ov.x = bf_pack(v.x, v.y);
        ov.y = bf_pack(v.z, v.w);
    } else {
        ov.x = 0u; ov.y = 0u;
    }
    *(uint2*)(g_w1 + e0) = ov;
}
__global__ void conv_w2_k(const float* __restrict__ w) {
    size_t idx = (size_t)blockIdx.x * 256 + threadIdx.x;
    if (idx >= (size_t)DI * E / 4) return;
    float4 v = *(const float4*)(w + idx * 4);
    uint2 ov;
    ov.x = bf_pack(v.x, v.y);
    ov.y = bf_pack(v.z, v.w);
    *(uint2*)(g_w2 + idx * 4) = ov;
}

// ---------------- rmsnorm (vectorized) ----------------
__global__ void rmsnorm_k(const float* __restrict__ x, const float* __restrict__ scale) {
    int r = blockIdx.x;
    int tid = threadIdx.x;
    const float4* xr4 = (const float4*)(x + (size_t)r * E);
    __shared__ float red[256];
    float ss = 0.f;
    #pragma unroll
    for (int i = 0; i < 2; i++) {
        float4 v = xr4[tid + i * 256];
        ss += v.x * v.x + v.y * v.y + v.z * v.z + v.w * v.w;
    }
    red[tid] = ss; __syncthreads();
    for (int s = 128; s > 0; s >>= 1) {
        if (tid < s) red[tid] += red[tid + s];
        __syncthreads();
    }
    float rstd = rsqrtf(red[0] / (float)E + 1e-6f);
    const float4* sc4 = (const float4*)scale;
    // 2048 / 8 = 256 groups: one per thread
    float4 a = xr4[tid * 2], b2 = xr4[tid * 2 + 1];
    float4 sa = sc4[tid * 2], sb = sc4[tid * 2 + 1];
    uint4 ov;
    ov.x = bf_pack(a.x * rstd * sa.x, a.y * rstd * sa.y);
    ov.y = bf_pack(a.z * rstd * sa.z, a.w * rstd * sa.w);
    ov.z = bf_pack(b2.x * rstd * sb.x, b2.y * rstd * sb.y);
    ov.w = bf_pack(b2.z * rstd * sb.z, b2.w * rstd * sb.w);
    *(uint4*)(g_h + (size_t)r * E + tid * 8) = ov;
}

// ---------------- bf16 WMMA GEMM, CTA 128x128, warp 64x32, BK=64, 3 stages ----------------
template<int MODE>
__global__ __launch_bounds__(256, 2) void gemm_bf16(
    const __nv_bfloat16* __restrict__ A, const __nv_bfloat16* __restrict__ Bw,
    void* __restrict__ Cout, const float* __restrict__ res,
    int K, int lda, int ldb, int ldc)
{
    extern __shared__ char smraw[];
    __nv_bfloat16* sbase = (__nv_bfloat16*)smraw;

    int tid = threadIdx.x;
    int wid = tid >> 5;
    int warp_m = wid >> 2;
    int warp_n = wid & 3;
    int row0 = blockIdx.y * 128;
    int col0 = blockIdx.x * 128;

    wmma::fragment<wmma::accumulator, 16, 16, 16, float> acc[4][2];
    if (MODE == 1) {
        #pragma unroll
        for (int i = 0; i < 4; i++)
            #pragma unroll
            for (int j = 0; j < 2; j++) {
                const float* p = res + (size_t)(row0 + warp_m * 64 + i * 16) * ldc
                                     + col0 + warp_n * 32 + j * 16;
                wmma::load_matrix_sync(acc[i][j], p, ldc, wmma::mem_row_major);
            }
    } else {
        #pragma unroll
        for (int i = 0; i < 4; i++)
            #pragma unroll
            for (int j = 0; j < 2; j++)
                wmma::fill_fragment(acc[i][j], 0.f);
    }

    int nst = K / GBK;

    auto load_stage = [&](int stage, int k0) {
        __nv_bfloat16* sA = sbase + stage * STAGE_EL;
        __nv_bfloat16* sB = sA + 128 * SA_STR;
        #pragma unroll
        for (int it = 0; it < 4; it++) {
            int u = tid + it * 256;
            int r = u >> 3, c = (u & 7) * 8;
            cpa16(sA + r * SA_STR + c, A + (size_t)(row0 + r) * lda + k0 + c);
        }
        #pragma unroll
        for (int it = 0; it < 4; it++) {
            int u = tid + it * 256;
            int r = u >> 4, c = (u & 15) * 8;
            cpa16(sB + r * SB_STR + c, Bw + (size_t)(k0 + r) * ldb + col0 + c);
        }
        CP_COMMIT();
    };

    load_stage(0, 0);
    if (nst > 1) load_stage(1, GBK);

    for (int s2 = 0; s2 < nst; s2++) {
        if (s2 >= nst - 1) { CP_WAIT0(); } else { CP_WAIT1(); }
        __syncthreads();
        if (s2 + 2 < nst) load_stage((s2 + 2) % 3, (s2 + 2) * GBK);

        __nv_bfloat16* sA = sbase + (s2 % 3) * STAGE_EL;
        __nv_bfloat16* sB = sA + 128 * SA_STR;
        #pragma unroll
        for (int kk = 0; kk < GBK; kk += 16) {
            wmma::fragment<wmma::matrix_a, 16, 16, 16, __nv_bfloat16, wmma::row_major> af[4];
            wmma::fragment<wmma::matrix_b, 16, 16, 16, __nv_bfloat16, wmma::row_major> bf[2];
            #pragma unroll
            for (int i = 0; i < 4; i++)
                wmma::load_matrix_sync(af[i], sA + (warp_m * 64 + i * 16) * SA_STR + kk, SA_STR);
            #pragma unroll
            for (int j = 0; j < 2; j++)
                wmma::load_matrix_sync(bf[j], sB + kk * SB_STR + warp_n * 32 + j * 16, SB_STR);
            #pragma unroll
            for (int i = 0; i < 4; i++)
                #pragma unroll
                for (int j = 0; j < 2; j++)
                    wmma::mma_sync(acc[i][j], af[i], bf[j], acc[i][j]);
        }
    }
    __syncthreads();

    if (MODE == 1) {
        float* out = (float*)Cout;
        #pragma unroll
        for (int i = 0; i < 4; i++)
            #pragma unroll
            for (int j = 0; j < 2; j++) {
                float* p = out + (size_t)(row0 + warp_m * 64 + i * 16) * ldc
                               + col0 + warp_n * 32 + j * 16;
                wmma::store_matrix_sync(p, acc[i][j], ldc, wmma::mem_row_major);
            }
    } else {
        float* sY = (float*)smraw;
        #pragma unroll
        for (int i = 0; i < 4; i++)
            #pragma unroll
            for (int j = 0; j < 2; j++)
                wmma::store_matrix_sync(sY + (warp_m * 64 + i * 16) * CY_STR
                                           + warp_n * 32 + j * 16,
                                        acc[i][j], CY_STR, wmma::mem_row_major);
        __syncthreads();
        __nv_bfloat16* out = (__nv_bfloat16*)Cout;
        #pragma unroll
        for (int it = 0; it < 8; it++) {
            int u = tid + it * 256;
            int r = u >> 4, c = (u & 15) * 8;
            const float* sp = sY + r * CY_STR + c;
            uint4 v;
            unsigned int* vp = (unsigned int*)&v;
            #pragma unroll
            for (int q = 0; q < 4; q++)
                vp[q] = bf_pack(sp[q * 2], sp[q * 2 + 1]);
            *(uint4*)(out + (size_t)(row0 + r) * ldc + col0 + c) = v;
        }
    }
}

// ---------------- SSD pass1 (WMMA) with fused conv+silu, async loads ----------------
__global__ __launch_bounds__(256) void ssd_pass1_k(
    const float* __restrict__ A_log, const float* __restrict__ dt_bias,
    const float* __restrict__ cw, const float* __restrict__ cb)
{
    extern __shared__ char smraw[];
    __nv_bfloat16* sB  = (__nv_bfloat16*)smraw;
    __nv_bfloat16* sC  = sB + QQ * TS;
    __nv_bfloat16* sX  = sC + QQ * TS;
    __nv_bfloat16* sWB = sX + QQ * TS;
    __nv_bfloat16* sMb = sWB + QQ * TS;
    float* sMf  = (float*)(sMb + QQ * MS);
    float* sdt  = sMf + QQ * MS;
    float* scum = sdt + QQ;
    float* sw   = scum + QQ;
    __nv_bfloat16* sP = sMb;   // alias: conv staging (67x128 bf16), dead before sMb/sMf used

    int h = blockIdx.x, c = blockIdx.y, b = blockIdx.z;
    int tid = threadIdx.x;
    int wid = tid >> 5;
    int r0 = b * TSEQ + c * QQ;
    int bstart = b * TSEQ;

    // ---- issue async loads: B, C tiles + conv window ----
    for (int u = tid; u < QQ * 16; u += 256) {
        int row = u >> 4, seg = (u & 15) * 8;
        size_t pb = (size_t)(r0 + row) * WPAD + 2 * DI + HH;
        cpa16(sB + row * TS + seg, g_proj + pb + seg);
        cpa16(sC + row * TS + seg, g_proj + pb + NS + seg);
    }
    for (int u = tid; u < 67 * 16; u += 256) {
        int row = u >> 4, seg = (u & 15) * 8;
        int gr = r0 - 3 + row;
        if (gr >= bstart)
            cpa16(sP + row * 128 + seg, g_proj + (size_t)gr * WPAD + DI + h * PP + seg);
        else {
            uint4 z = {0u, 0u, 0u, 0u};
            *(uint4*)(sP + row * 128 + seg) = z;
        }
    }
    CP_COMMIT();

    // ---- dt + cumulative log decay (overlaps async loads) ----
    if (tid < QQ) {
        float d = __bfloat162float(g_proj[(size_t)(r0 + tid) * WPAD + 2 * DI + h]) + dt_bias[h];
        float dt = (d > 20.f) ? d : log1pf(__expf(d));
        sdt[tid] = dt;
        scum[tid] = -__expf(A_log[h]) * dt;
    }
    __syncthreads();
    for (int off = 1; off < QQ; off <<= 1) {
        float add = 0.f;
        if (tid < QQ && tid >= off) add = scum[tid - off];
        __syncthreads();
        if (tid < QQ) scum[tid] += add;
        __syncthreads();
    }
    if (tid < QQ) {
        g_cum[(size_t)(r0 + tid) * HH + h] = scum[tid];
        float clast = scum[QQ - 1];
        sw[tid] = __expf(clast - scum[tid]) * sdt[tid];
        if (tid == 0) g_cdecay[(b * NC + c) * HH + h] = __expf(clast);
    }
    CP_WAIT0();
    __syncthreads();

    // ---- build sWB (vectorized) ----
    for (int v = tid; v < QQ * 16; v += 256) {
        int row = v >> 4, c8 = (v & 15) * 8;
        float wv = sw[row];
        uint4 bv = *(uint4*)(sB + row * TS + c8);
        const unsigned int* bu = (const unsigned int*)&bv;
        uint4 ov;
        unsigned int* op = (unsigned int*)&ov;
        #pragma unroll
        for (int q = 0; q < 4; q++)
            op[q] = bf_pack(bf_lo(bu[q]) * wv, bf_hi(bu[q]) * wv);
        *(uint4*)(sWB + row * TS + c8) = ov;
    }

    // ---- build sX via conv + silu from staged sP ----
    for (int v = tid; v < QQ * 16; v += 256) {
        int row = v >> 4, c8 = (v & 15) * 8;
        int d0 = h * PP + c8;
        float acc[8];
        const float4* cbp = (const float4*)(cb + d0);
        float4 cb0 = cbp[0], cb1 = cbp[1];
        acc[0] = cb0.x; acc[1] = cb0.y; acc[2] = cb0.z; acc[3] = cb0.w;
        acc[4] = cb1.x; acc[5] = cb1.y; acc[6] = cb1.z; acc[7] = cb1.w;
        #pragma unroll
        for (int k = 0; k < DCONV; k++) {
            uint4 pv = *(uint4*)(sP + (row + k) * 128 + c8);
            const unsigned int* pu = (const unsigned int*)&pv;
            const float4* wp = (const float4*)(cw + k * DI + d0);
            float4 w0 = wp[0], w1 = wp[1];
            float wv[8] = {w0.x, w0.y, w0.z, w0.w, w1.x, w1.y, w1.z, w1.w};
            #pragma unroll
            for (int q = 0; q < 4; q++) {
                acc[q * 2]     += bf_lo(pu[q]) * wv[q * 2];
                acc[q * 2 + 1] += bf_hi(pu[q]) * wv[q * 2 + 1];
            }
        }
        uint4 ov;
        unsigned int* op = (unsigned int*)&ov;
        #pragma unroll
        for (int q = 0; q < 4; q++) {
            float a0 = acc[q * 2],     s0 = a0 / (1.f + __expf(-a0));
            float a1 = acc[q * 2 + 1], s1 = a1 / (1.f + __expf(-a1));
            op[q] = bf_pack(s0, s1);
        }
        *(uint4*)(sX + row * TS + c8) = ov;
        *(uint4*)(g_act + (size_t)(r0 + row) * DI + d0) = ov;
    }
    __syncthreads();   // sP dead from here; sMb/sMf free to use

    // ---- CB = C @ B^T ----
    {
        int wm = wid >> 1, wn = wid & 1;
        wmma::fragment<wmma::accumulator, 16, 16, 16, float> acc2[2];
        wmma::fill_fragment(acc2[0], 0.f);
        wmma::fill_fragment(acc2[1], 0.f);
        #pragma unroll
        for (int k = 0; k < 8; k++) {
            wmma::fragment<wmma::matrix_a, 16, 16, 16, __nv_bfloat16, wmma::row_major> a;
            wmma::load_matrix_sync(a, sC + (wm * 16) * TS + k * 16, TS);
            #pragma unroll
            for (int j2 = 0; j2 < 2; j2++) {
                wmma::fragment<wmma::matrix_b, 16, 16, 16, __nv_bfloat16, wmma::col_major> bfr;
                wmma::load_matrix_sync(bfr, sB + (wn * 32 + j2 * 16) * TS + k * 16, TS);
                wmma::mma_sync(acc2[j2], a, bfr, acc2[j2]);
            }
        }
        #pragma unroll
        for (int j2 = 0; j2 < 2; j2++)
            wmma::store_matrix_sync(sMf + (wm * 16) * MS + wn * 32 + j2 * 16, acc2[j2],
                                    MS, wmma::mem_row_major);
    }
    __syncthreads();

    for (int e = tid; e < QQ * QQ; e += 256) {
        int i = e >> 6, j = e & 63;
        float m = 0.f;
        if (j <= i)
            m = sMf[i * MS + j] * __expf(scum[i] - scum[j]) * sdt[j];
        sMb[i * MS + j] = __float2bfloat16(m);
    }
    __syncthreads();

    // ---- y_intra = M @ X -> stage fp32 -> bf16 g_y ----
    {
        int wm = wid >> 1, wn = wid & 1;
        wmma::fragment<wmma::accumulator, 16, 16, 16, float> acc4[4];
        #pragma unroll
        for (int j = 0; j < 4; j++) wmma::fill_fragment(acc4[j], 0.f);
        #pragma unroll
        for (int k = 0; k < 4; k++) {
            wmma::fragment<wmma::matrix_a, 16, 16, 16, __nv_bfloat16, wmma::row_major> a;
            wmma::load_matrix_sync(a, sMb + (wm * 16) * MS + k * 16, MS);
            #pragma unroll
            for (int jj = 0; jj < 4; jj++) {
                wmma::fragment<wmma::matrix_b, 16, 16, 16, __nv_bfloat16, wmma::row_major> bfr;
                wmma::load_matrix_sync(bfr, sX + (k * 16) * TS + wn * 64 + jj * 16, TS);
                wmma::mma_sync(acc4[jj], a, bfr, acc4[jj]);
            }
        }
        float* sYst = (float*)smraw;   // 64*132*4 = 33792 <= sB+sC (34816)
        #pragma unroll
        for (int jj = 0; jj < 4; jj++)
            wmma::store_matrix_sync(sYst + (wm * 16) * YS + wn * 64 + jj * 16,
                                    acc4[jj], YS, wmma::mem_row_major);
        __syncthreads();
        #pragma unroll
        for (int it = 0; it < 4; it++) {
            int u = tid + it * 256;
            int r = u >> 4, cc = (u & 15) * 8;
            const float* sp = sYst + r * YS + cc;
            uint4 vv;
            unsigned int* vp = (unsigned int*)&vv;
            #pragma unroll
            for (int q = 0; q < 4; q++)
                vp[q] = bf_pack(sp[q * 2], sp[q * 2 + 1]);
            *(uint4*)(g_y + (size_t)(r0 + r) * DI + h * PP + cc) = vv;
        }
    }

    // ---- state = WB^T @ X -> stage fp32 -> bf16 g_state ----
    {
        int wm = wid >> 1, wn = wid & 1;
        size_t sbase = (size_t)((b * NC + c) * HH + h) * (NS * PP);
        wmma::fragment<wmma::accumulator, 16, 16, 16, float> accs[2][4];
        #pragma unroll
        for (int i2 = 0; i2 < 2; i2++)
            #pragma unroll
            for (int jj = 0; jj < 4; jj++) wmma::fill_fragment(accs[i2][jj], 0.f);
        #pragma unroll
        for (int k = 0; k < 4; k++) {
            wmma::fragment<wmma::matrix_a, 16, 16, 16, __nv_bfloat16, wmma::col_major> a[2];
            #pragma unroll
            for (int i2 = 0; i2 < 2; i2++)
                wmma::load_matrix_sync(a[i2], sWB + (k * 16) * TS + wm * 32 + i2 * 16, TS);
            #pragma unroll
            for (int jj = 0; jj < 4; jj++) {
                wmma::fragment<wmma::matrix_b, 16, 16, 16, __nv_bfloat16, wmma::row_major> bfr;
                wmma::load_matrix_sync(bfr, sX + (k * 16) * TS + wn * 64 + jj * 16, TS);
                #pragma unroll
                for (int i2 = 0; i2 < 2; i2++)
                    wmma::mma_sync(accs[i2][jj], a[i2], bfr, accs[i2][jj]);
            }
        }
        __syncthreads();
        float* sSt = (float*)smraw;   // 128*132*4 = 67584 <= sB..sWB (69632)
        #pragma unroll
        for (int i2 = 0; i2 < 2; i2++)
            #pragma unroll
            for (int jj = 0; jj < 4; jj++)
                wmma::store_matrix_sync(sSt + (wm * 32 + i2 * 16) * YS
                                            + wn * 64 + jj * 16,
                                        accs[i2][jj], YS, wmma::mem_row_major);
        __syncthreads();
        #pragma unroll
        for (int it = 0; it < 8; it++) {
            int u = tid + it * 256;
            int r = u >> 4, cc = (u & 15) * 8;
            const float* sp = sSt + r * YS + cc;
            uint4 vv;
            unsigned int* vp = (unsigned int*)&vv;
            #pragma unroll
            for (int q = 0; q < 4; q++)
                vp[q] = bf_pack(sp[q * 2], sp[q * 2 + 1]);
            *(uint4*)(g_state + sbase + (size_t)r * PP + cc) = vv;
        }
    }
}

// ---------------- SSD pass2: inter-chunk scan (vectorized bf16, fp32 regs) ----------------
__global__ __launch_bounds__(512) void ssd_scan_k() {
    int h = blockIdx.x, b = blockIdx.y, sl = blockIdx.z;
    int tid = threadIdx.x;
    int off = sl * 4096 + tid * 8;
    float st[8];
    #pragma unroll
    for (int k = 0; k < 8; k++) st[k] = 0.f;
    for (int c = 0; c < NC; c++) {
        size_t base = (size_t)((b * NC + c) * HH + h) * (NS * PP) + off;
        float dcy = g_cdecay[(b * NC + c) * HH + h];
        uint4 v = *(uint4*)(g_state + base);
        const unsigned int* vu = (const unsigned int*)&v;
        uint4 ov;
        unsigned int* op = (unsigned int*)&ov;
        #pragma unroll
        for (int q = 0; q < 4; q++) {
            float l0 = bf_lo(vu[q]), l1 = bf_hi(vu[q]);
            op[q] = bf_pack(st[q * 2], st[q * 2 + 1]);
            st[q * 2]     = fmaf(dcy, st[q * 2], l0);
            st[q * 2 + 1] = fmaf(dcy, st[q * 2 + 1], l1);
        }
        *(uint4*)(g_state + base) = ov;
    }
}

// ---------------- SSD pass3 (WMMA, async loads, vector epilogue) ----------------
__global__ __launch_bounds__(256) void ssd_pass3_k(const float* __restrict__ Dv) {
    extern __shared__ char smraw[];
    __nv_bfloat16* sC = (__nv_bfloat16*)smraw;
    __nv_bfloat16* sS = sC + QQ * TS;
    float* sY   = (float*)(sS + NS * TS);
    float* scum = sY + QQ * YS;

    int h = blockIdx.x, c = blockIdx.y, b = blockIdx.z;
    int tid = threadIdx.x;
    int wid = tid >> 5;
    int r0 = b * TSEQ + c * QQ;
    size_t sbase = (size_t)((b * NC + c) * HH + h) * (NS * PP);

    for (int u = tid; u < NS * 16; u += 256) {
        int row = u >> 4, seg = (u & 15) * 8;
        cpa16(sS + row * TS + seg, g_state + sbase + (size_t)row * PP + seg);
    }
    for (int u = tid; u < QQ * 16; u += 256) {
        int row = u >> 4, seg = (u & 15) * 8;
        cpa16(sC + row * TS + seg,
              g_proj + (size_t)(r0 + row) * WPAD + 2 * DI + HH + NS + seg);
    }
    CP_COMMIT();
    if (tid < QQ) scum[tid] = g_cum[(size_t)(r0 + tid) * HH + h];
    CP_WAIT0();
    __syncthreads();

    {
        int wm = wid >> 1, wn = wid & 1;
        wmma::fragment<wmma::accumulator, 16, 16, 16, float> acc4[4];
        #pragma unroll
        for (int j = 0; j < 4; j++) wmma::fill_fragment(acc4[j], 0.f);
        #pragma unroll
        for (int k = 0; k < 8; k++) {
            wmma::fragment<wmma::matrix_a, 16, 16, 16, __nv_bfloat16, wmma::row_major> a;
            wmma::load_matrix_sync(a, sC + (wm * 16) * TS + k * 16, TS);
            #pragma unroll
            for (int jj = 0; jj < 4; jj++) {
                wmma::fragment<wmma::matrix_b, 16, 16, 16, __nv_bfloat16, wmma::row_major> bfr;
                wmma::load_matrix_sync(bfr, sS + (k * 16) * TS + wn * 64 + jj * 16, TS);
                wmma::mma_sync(acc4[jj], a, bfr, acc4[jj]);
            }
        }
        #pragma unroll
        for (int jj = 0; jj < 4; jj++)
            wmma::store_matrix_sync(sY + (wm * 16) * YS + wn * 64 + jj * 16, acc4[jj],
                                    YS, wmma::mem_row_major);
    }
    __syncthreads();

    // vectorized epilogue
    for (int u = tid; u < QQ * 16; u += 256) {
        int i = u >> 4, p8 = (u & 15) * 8;
        float ydec = __expf(scum[i]);
        int d0 = h * PP + p8;
        size_t r = (size_t)(r0 + i);
        uint4 yv = *(uint4*)(g_y + r * DI + d0);
        uint4 av = *(uint4*)(g_act + r * DI + d0);
        uint4 gv = *(uint4*)(g_proj + r * WPAD + d0);
        const unsigned int* yu = (const unsigned int*)&yv;
        const unsigned int* au = (const unsigned int*)&av;
        const unsigned int* gu = (const unsigned int*)&gv;
        const float4* dp = (const float4*)(Dv + d0);
        float4 dv0 = dp[0], dv1 = dp[1];
        float dvv[8] = {dv0.x, dv0.y, dv0.z, dv0.w, dv1.x, dv1.y, dv1.z, dv1.w};
        const float* syp = sY + i * YS + p8;
        uint4 ov;
        unsigned int* op = (unsigned int*)&ov;
        #pragma unroll
        for (int q = 0; q < 4; q++) {
            float v0 = bf_lo(yu[q]) + ydec * syp[q * 2]     + dvv[q * 2]     * bf_lo(au[q]);
            float v1 = bf_hi(yu[q]) + ydec * syp[q * 2 + 1] + dvv[q * 2 + 1] * bf_hi(au[q]);
            float gt0 = bf_lo(gu[q]), gt1 = bf_hi(gu[q]);
            v0 *= gt0 / (1.f + __expf(-gt0));
            v1 *= gt1 / (1.f + __expf(-gt1));
            op[q] = bf_pack(v0, v1);
        }
        *(uint4*)(g_yb + r * DI + d0) = ov;
    }
}

// ---------------- launch ----------------
extern "C" void kernel_launch(void* const* d_in, const int* in_sizes, int n_in,
                              void* d_out, int out_size) {
    const float* x         = (const float*)d_in[0];
    const float* normscale = (const float*)d_in[1];
    const float* w1        = (const float*)d_in[2];
    const float* convw     = (const float*)d_in[3];
    const float* convb     = (const float*)d_in[4];
    const float* A_log     = (const float*)d_in[5];
    const float* dt_bias   = (const float*)d_in[6];
    const float* Dv        = (const float*)d_in[7];
    const float* w2        = (const float*)d_in[8];
    float* out             = (float*)d_out;

    void *p_h, *p_w1, *p_w2, *p_proj, *p_yb;
    cudaGetSymbolAddress(&p_h, g_h);
    cudaGetSymbolAddress(&p_w1, g_w1);
    cudaGetSymbolAddress(&p_w2, g_w2);
    cudaGetSymbolAddress(&p_proj, g_proj);
    cudaGetSymbolAddress(&p_yb, g_yb);

    const int smemG = 3 * STAGE_EL * 2;                          // 107520
    const int smem1 = (4 * QQ * TS + QQ * MS) * 2 + (QQ * MS + 3 * QQ) * 4;
    const int smem3 = (QQ * TS + NS * TS) * 2 + (QQ * YS + QQ) * 4;
    cudaFuncSetAttribute(gemm_bf16<0>, cudaFuncAttributeMaxDynamicSharedMemorySize, smemG);
    cudaFuncSetAttribute(gemm_bf16<1>, cudaFuncAttributeMaxDynamicSharedMemorySize, smemG);
    cudaFuncSetAttribute(ssd_pass1_k, cudaFuncAttributeMaxDynamicSharedMemorySize, smem1);
    cudaFuncSetAttribute(ssd_pass3_k, cudaFuncAttributeMaxDynamicSharedMemorySize, smem3);

    {
        size_t n1 = (size_t)E * WPAD / 4;
        conv_w1_k<<<(unsigned)((n1 + 255) / 256), 256>>>(w1);
        size_t n2 = (size_t)DI * E / 4;
        conv_w2_k<<<(unsigned)((n2 + 255) / 256), 256>>>(w2);
    }
    rmsnorm_k<<<R_TOT, 256>>>(x, normscale);
    {
        dim3 grid(WPAD / 128, R_TOT / 128);
        gemm_bf16<0><<<grid, 256, smemG>>>((const __nv_bfloat16*)p_h,
                                           (const __nv_bfloat16*)p_w1,
                                           p_proj, nullptr, E, E, WPAD, WPAD);
    }
    {
        dim3 grid(HH, NC, BATCH);
        ssd_pass1_k<<<grid, 256, smem1>>>(A_log, dt_bias, convw, convb);
    }
    {
        dim3 grid(HH, BATCH, 4);
        ssd_scan_k<<<grid, 512>>>();
    }
    {
        dim3 grid(HH, NC, BATCH);
        ssd_pass3_k<<<grid, 256, smem3>>>(Dv);
    }
    {
        dim3 grid(E / 128, R_TOT / 128);
        gemm_bf16<1><<<grid, 256, smemG>>>((const __nv_bfloat16*)p_yb,
                                           (const __nv_bfloat16*)p_w2,
                                           out, x, DI, DI, E, E);
    }
}